// round 7
// baseline (speedup 1.0000x reference)
#include <cuda_runtime.h>
#include <cstdint>

typedef unsigned long long ull;

#define NB 2048
#define NT 200
#define NE 128
#define NH1 64
#define NH2 32
#define NEG_INF (-4294967295.0f)

#define SK_STRIDE 132    // floats per K row (padded)
#define SWP_ROW   96     // ull per Weff e-pair row: 16 chunks of 4 ull at stride 6
#define SH_STRIDE 68     // floats per H1 row (padded)
#define SW2T_STRIDE 70   // floats per W2^T row (padded, conflict-free LDS.64)

#define OFF_SK    0        // 105600 B
#define OFF_SWP   105600   // 49152 B
#define OFF_SH    154752   // 54400 B
#define OFF_SW2T  209152   // 8960 B
#define OFF_SQ    218112   // 512 B
#define OFF_SQBP  218624   // 2048 B
#define OFF_SQB   220672   // 256 B
#define OFF_SS    220928   // 800 B
#define OFF_SB2   221728   // 128 B
#define OFF_SW3   221856   // 128 B
#define OFF_SRED  221984   // 128 B
#define OFF_SPOOL 222112   // 4096 B
#define SMEM_TOTAL 226208

__device__ __forceinline__ ull fma2(ull a, ull b, ull c) {
    ull d;
    asm("fma.rn.f32x2 %0, %1, %2, %3;" : "=l"(d) : "l"(a), "l"(b), "l"(c));
    return d;
}
__device__ __forceinline__ ull pack2(float x) {
    ull d; unsigned u = __float_as_uint(x);
    asm("mov.b64 %0, {%1, %1};" : "=l"(d) : "r"(u));
    return d;
}
__device__ __forceinline__ float2 unpack2(ull v) {
    float2 r;
    asm("mov.b64 {%0, %1}, %2;" : "=f"(r.x), "=f"(r.y) : "l"(v));
    return r;
}
__device__ __forceinline__ void cp_async16(void* smem_dst, const void* gmem_src) {
    uint32_t s = (uint32_t)__cvta_generic_to_shared(smem_dst);
    asm volatile("cp.async.cg.shared.global [%0], [%1], 16;" :: "r"(s), "l"(gmem_src));
}

__global__ __launch_bounds__(1024, 1)
void attn_kernel(const float* __restrict__ queries, const float* __restrict__ keys,
                 const int* __restrict__ keys_id, const float* __restrict__ W1,
                 const float* __restrict__ b1, const float* __restrict__ W2,
                 const float* __restrict__ b2, const float* __restrict__ W3,
                 const float* __restrict__ b3, float* __restrict__ out)
{
    extern __shared__ char smem[];
    float* sK    = (float*)(smem + OFF_SK);
    ull*   sWp   = (ull*)  (smem + OFF_SWP);
    float* sH    = (float*)(smem + OFF_SH);
    float* sW2t  = (float*)(smem + OFF_SW2T);
    float* sQ    = (float*)(smem + OFF_SQ);
    float* sQBp  = (float*)(smem + OFF_SQBP);
    float* sQB   = (float*)(smem + OFF_SQB);
    float* sS    = (float*)(smem + OFF_SS);
    float* sB2   = (float*)(smem + OFF_SB2);
    float* sW3v  = (float*)(smem + OFF_SW3);
    float* sRed  = (float*)(smem + OFF_SRED);
    float* sPool = (float*)(smem + OFF_SPOOL);

    const int tid = threadIdx.x;
    const int b = blockIdx.x;

    // ---- Stage A: async K tile load (overlapped with Weff build) ----
    {
        const float4* gK = (const float4*)(keys + (size_t)b * NT * NE);
        #pragma unroll 4
        for (int i = tid; i < NT * NE / 4; i += 1024) {
            int t = i >> 5;        // 32 float4 per row
            int c = i & 31;
            cp_async16(sK + t * SK_STRIDE + 4 * c, gK + i);
        }
        asm volatile("cp.async.commit_group;");
    }
    if (tid < NE) sQ[tid] = queries[b * NE + tid];
    for (int i = tid; i < NH1 * NH2; i += 1024) {
        int h = i >> 5, k = i & 31;
        sW2t[k * SW2T_STRIDE + h] = W2[i];
    }
    if (tid < NH2) { sB2[tid] = b2[tid]; sW3v[tid] = W3[tid]; }
    __syncthreads();   // sQ visible for stage B

    // ---- Stage B: Weff = (W1b - W1c) + q .* W1d, e-pair interleaved; qbias ----
    for (int i = tid; i < NE * NH1; i += 1024) {
        int e = i >> 6, h = i & 63;
        float wb = W1[(NE + e) * NH1 + h];
        float wc = W1[(2 * NE + e) * NH1 + h];
        float wd = W1[(3 * NE + e) * NH1 + h];
        // layout: ull index = (e/2)*96 + (h/4)*6 + (h&3); lane = e&1
        float* dst = (float*)(sWp + (e >> 1) * SWP_ROW + (h >> 2) * 6 + (h & 3));
        dst[e & 1] = wb - wc + sQ[e] * wd;
    }
    if (tid < 512) {
        int h = tid & 63, seg = tid >> 6;   // 8 segments of 16 e
        float p = 0.f;
        int e0 = seg * 16;
        #pragma unroll 4
        for (int e = e0; e < e0 + 16; ++e)
            p += sQ[e] * (W1[e * NH1 + h] + W1[(2 * NE + e) * NH1 + h]);
        sQBp[seg * 64 + h] = p;
    }
    asm volatile("cp.async.wait_group 0;");
    __syncthreads();   // sK, sWp, sQBp visible

    if (tid < NH1) {
        float s = b1[tid];
        #pragma unroll
        for (int i = 0; i < 8; ++i) s += sQBp[i * 64 + tid];
        sQB[tid] = s;
    }
    __syncthreads();

    // ---- Stage D: h1 = relu(K @ Weff + qbias). 4t x 4h tiles, single pass ----
    if (tid < 800) {
        int hb = tid & 15;        // 16 h-blocks of 4
        int tb = tid >> 4;        // 0..49 ; rows tb, tb+50, tb+100, tb+150
        int h0 = hb * 4;
        ull acc[4][4];
        #pragma unroll
        for (int i = 0; i < 4; ++i)
            #pragma unroll
            for (int j = 0; j < 4; ++j) acc[i][j] = 0ull;

        const ull* k0 = (const ull*)sK + tb * (SK_STRIDE / 2);  // 66 ull/row
        const ull* wbase = sWp + hb * 6;
        #pragma unroll 4
        for (int ep = 0; ep < NE / 2; ++ep) {
            ull kk0 = k0[ep];
            ull kk1 = k0[50  * (SK_STRIDE / 2) + ep];
            ull kk2 = k0[100 * (SK_STRIDE / 2) + ep];
            ull kk3 = k0[150 * (SK_STRIDE / 2) + ep];
            const ulonglong2* wp = (const ulonglong2*)(wbase + ep * SWP_ROW);
            ulonglong2 wa = wp[0], wb = wp[1];  // h0, h0+1, h0+2, h0+3
            acc[0][0] = fma2(kk0, wa.x, acc[0][0]);
            acc[0][1] = fma2(kk0, wa.y, acc[0][1]);
            acc[0][2] = fma2(kk0, wb.x, acc[0][2]);
            acc[0][3] = fma2(kk0, wb.y, acc[0][3]);
            acc[1][0] = fma2(kk1, wa.x, acc[1][0]);
            acc[1][1] = fma2(kk1, wa.y, acc[1][1]);
            acc[1][2] = fma2(kk1, wb.x, acc[1][2]);
            acc[1][3] = fma2(kk1, wb.y, acc[1][3]);
            acc[2][0] = fma2(kk2, wa.x, acc[2][0]);
            acc[2][1] = fma2(kk2, wa.y, acc[2][1]);
            acc[2][2] = fma2(kk2, wb.x, acc[2][2]);
            acc[2][3] = fma2(kk2, wb.y, acc[2][3]);
            acc[3][0] = fma2(kk3, wa.x, acc[3][0]);
            acc[3][1] = fma2(kk3, wa.y, acc[3][1]);
            acc[3][2] = fma2(kk3, wb.x, acc[3][2]);
            acc[3][3] = fma2(kk3, wb.y, acc[3][3]);
        }
        float qb0 = sQB[h0], qb1 = sQB[h0 + 1], qb2 = sQB[h0 + 2], qb3 = sQB[h0 + 3];
        #pragma unroll
        for (int i = 0; i < 4; ++i) {
            float* dst = sH + (tb + 50 * i) * SH_STRIDE + h0;
            float2 v0 = unpack2(acc[i][0]);
            float2 v1 = unpack2(acc[i][1]);
            float2 v2 = unpack2(acc[i][2]);
            float2 v3 = unpack2(acc[i][3]);
            dst[0] = fmaxf(v0.x + v0.y + qb0, 0.f);
            dst[1] = fmaxf(v1.x + v1.y + qb1, 0.f);
            dst[2] = fmaxf(v2.x + v2.y + qb2, 0.f);
            dst[3] = fmaxf(v3.x + v3.y + qb3, 0.f);
        }
    }
    __syncthreads();

    // ---- Stage E: scores. warp = token stream, lane = H2 unit ----
    {
        int warp = tid >> 5, lane = tid & 31;
        float w3v = sW3v[lane];
        float b2v = sB2[lane];
        float b3v = b3[0];
        const ull* wrow = (const ull*)(sW2t + lane * SW2T_STRIDE);
        for (int t = warp; t < NT; t += 32) {
            const ull* hrow = (const ull*)(sH + t * SH_STRIDE);
            ull a2 = 0ull;
            #pragma unroll
            for (int j = 0; j < 32; ++j)
                a2 = fma2(hrow[j], wrow[j], a2);
            float2 v = unpack2(a2);
            float h2v = fmaxf(v.x + v.y + b2v, 0.f);
            float contrib = h2v * w3v;
            #pragma unroll
            for (int o = 16; o; o >>= 1)
                contrib += __shfl_xor_sync(0xffffffffu, contrib, o);
            if (lane == 0) {
                float sc = contrib + b3v;
                sS[t] = (keys_id[b * NT + t] != 0) ? sc : NEG_INF;
            }
        }
    }
    __syncthreads();

    // ---- Stage F: masked softmax over T ----
    {
        float v = (tid < NT) ? sS[tid] : -3.0e38f;
        float m = v;
        #pragma unroll
        for (int o = 16; o; o >>= 1) m = fmaxf(m, __shfl_xor_sync(0xffffffffu, m, o));
        if ((tid & 31) == 0) sRed[tid >> 5] = m;
        __syncthreads();
        float mx = sRed[0];
        #pragma unroll
        for (int i = 1; i < 32; ++i) mx = fmaxf(mx, sRed[i]);
        float p = (tid < NT) ? __expf(v - mx) : 0.f;
        float s = p;
        #pragma unroll
        for (int o = 16; o; o >>= 1) s += __shfl_xor_sync(0xffffffffu, s, o);
        __syncthreads();                  // sRed reuse barrier
        if ((tid & 31) == 0) sRed[tid >> 5] = s;
        __syncthreads();
        float tot = 0.f;
        #pragma unroll
        for (int i = 0; i < 32; ++i) tot += sRed[i];
        if (tid < NT) sS[tid] = p / tot;
    }
    __syncthreads();

    // ---- Stage G: out[e] = (1/T) * sum_t w[t] * K[t][e] ----
    if (tid < 512) {
        int pr = tid & 63;      // e-pair index
        int seg = tid >> 6;     // 8 t-segments of 25
        ull a2 = 0ull;
        int t0 = seg * 25;
        #pragma unroll 5
        for (int t = t0; t < t0 + 25; ++t) {
            ull wv = pack2(sS[t]);
            const ull* krow = (const ull*)(sK + t * SK_STRIDE);
            a2 = fma2(wv, krow[pr], a2);
        }
        float2 v = unpack2(a2);
        sPool[seg * 128 + 2 * pr]     = v.x;
        sPool[seg * 128 + 2 * pr + 1] = v.y;
    }
    __syncthreads();
    if (tid < NE) {
        float r = 0.f;
        #pragma unroll
        for (int i = 0; i < 8; ++i) r += sPool[i * 128 + tid];
        out[b * NE + tid] = r * (1.0f / NT);
    }
}

extern "C" void kernel_launch(void* const* d_in, const int* in_sizes, int n_in,
                              void* d_out, int out_size) {
    const float* queries = (const float*)d_in[0];
    const float* keys    = (const float*)d_in[1];
    const int*   keys_id = (const int*)  d_in[2];
    const float* W1      = (const float*)d_in[3];
    const float* b1      = (const float*)d_in[4];
    const float* W2      = (const float*)d_in[5];
    const float* b2      = (const float*)d_in[6];
    const float* W3      = (const float*)d_in[7];
    const float* b3      = (const float*)d_in[8];
    float* out = (float*)d_out;

    cudaFuncSetAttribute(attn_kernel,
                         cudaFuncAttributeMaxDynamicSharedMemorySize, SMEM_TOTAL);
    attn_kernel<<<NB, 1024, SMEM_TOTAL>>>(queries, keys, keys_id,
                                          W1, b1, W2, b2, W3, b3, out);
}

// round 10
// speedup vs baseline: 1.0181x; 1.0181x over previous
#include <cuda_runtime.h>
#include <cstdint>

typedef unsigned long long ull;

#define NB 2048
#define NT 200
#define NE 128
#define NH1 64
#define NH2 32
#define NEG_INF (-4294967295.0f)

#define SK_STRIDE 130     // floats per K row; 65 ull, odd -> conflict-free LDS.64
#define SK_ULL    65
#define SH_STRIDE 68      // floats per H1 row (padded)
#define SW2T_STRIDE 70    // floats per W2^T row (padded, conflict-free LDS.64)

#define OFF_SK    0        // 104000 B (200*65*8)
#define OFF_SWP   104000   // 32768 B (64 ep * 64 h * 8)
#define OFF_SH    136768   // 54400 B
#define OFF_SW2T  191168   // 8960 B
#define OFF_SQ    200128   // 512 B
#define OFF_SQBP  200640   // 2048 B
#define OFF_SQB   202688   // 256 B
#define OFF_SS    202944   // 800 B
#define OFF_SB2   203744   // 128 B
#define OFF_SW3   203872   // 128 B
#define OFF_SRED  204000   // 128 B
#define OFF_SPOOL 204128   // 4096 B
#define SMEM_TOTAL 208224

__device__ __forceinline__ ull fma2(ull a, ull b, ull c) {
    ull d;
    asm("fma.rn.f32x2 %0, %1, %2, %3;" : "=l"(d) : "l"(a), "l"(b), "l"(c));
    return d;
}
__device__ __forceinline__ ull pack2(float x) {
    ull d; unsigned u = __float_as_uint(x);
    asm("mov.b64 %0, {%1, %1};" : "=l"(d) : "r"(u));
    return d;
}
__device__ __forceinline__ float2 unpack2(ull v) {
    float2 r;
    asm("mov.b64 {%0, %1}, %2;" : "=f"(r.x), "=f"(r.y) : "l"(v));
    return r;
}
__device__ __forceinline__ void cp_async8(void* smem_dst, const void* gmem_src) {
    uint32_t s = (uint32_t)__cvta_generic_to_shared(smem_dst);
    asm volatile("cp.async.ca.shared.global [%0], [%1], 8;" :: "r"(s), "l"(gmem_src));
}

__global__ __launch_bounds__(512, 1)
void attn_kernel(const float* __restrict__ queries, const float* __restrict__ keys,
                 const int* __restrict__ keys_id, const float* __restrict__ W1,
                 const float* __restrict__ b1, const float* __restrict__ W2,
                 const float* __restrict__ b2, const float* __restrict__ W3,
                 const float* __restrict__ b3, float* __restrict__ out)
{
    extern __shared__ char smem[];
    float* sK    = (float*)(smem + OFF_SK);
    ull*   sWp   = (ull*)  (smem + OFF_SWP);   // [ep][h] : (W[2ep][h], W[2ep+1][h])
    float* sH    = (float*)(smem + OFF_SH);
    float* sW2t  = (float*)(smem + OFF_SW2T);
    float* sQ    = (float*)(smem + OFF_SQ);
    float* sQBp  = (float*)(smem + OFF_SQBP);
    float* sQB   = (float*)(smem + OFF_SQB);
    float* sS    = (float*)(smem + OFF_SS);
    float* sB2   = (float*)(smem + OFF_SB2);
    float* sW3v  = (float*)(smem + OFF_SW3);
    float* sRed  = (float*)(smem + OFF_SRED);
    float* sPool = (float*)(smem + OFF_SPOOL);

    const int tid = threadIdx.x;
    const int b = blockIdx.x;

    // ---- Stage A: async K tile load (8B chunks; 65-ull padded rows) ----
    {
        const ull* gK = (const ull*)(keys + (size_t)b * NT * NE);
        ull* dK = (ull*)sK;
        #pragma unroll 5
        for (int i = tid; i < NT * NE / 2; i += 512) {
            int t = i >> 6;        // 64 ull per source row
            int c = i & 63;
            cp_async8(dK + t * SK_ULL + c, gK + i);
        }
        asm volatile("cp.async.commit_group;");
    }
    if (tid < NE) sQ[tid] = queries[b * NE + tid];
    for (int i = tid; i < NH1 * NH2; i += 512) {
        int h = i >> 5, k = i & 31;
        sW2t[k * SW2T_STRIDE + h] = W2[i];
    }
    if (tid < NH2) { sB2[tid] = b2[tid]; sW3v[tid] = W3[tid]; }
    __syncthreads();   // sQ visible for stage B

    // ---- Stage B: Weff = (W1b - W1c) + q .* W1d, e-pair-major; qbias ----
    for (int i = tid; i < NE * NH1; i += 512) {
        int e = i >> 6, h = i & 63;
        float wb = W1[(NE + e) * NH1 + h];
        float wc = W1[(2 * NE + e) * NH1 + h];
        float wd = W1[(3 * NE + e) * NH1 + h];
        float* dst = (float*)(sWp + (e >> 1) * 64 + h);
        dst[e & 1] = wb - wc + sQ[e] * wd;
    }
    {
        int h = tid & 63, seg = tid >> 6;   // 8 segments of 16 e
        float p = 0.f;
        int e0 = seg * 16;
        #pragma unroll 4
        for (int e = e0; e < e0 + 16; ++e)
            p += sQ[e] * (W1[e * NH1 + h] + W1[(2 * NE + e) * NH1 + h]);
        sQBp[seg * 64 + h] = p;
    }
    asm volatile("cp.async.wait_group 0;");
    __syncthreads();   // sK, sWp, sQBp visible

    if (tid < NH1) {
        float s = b1[tid];
        #pragma unroll
        for (int i = 0; i < 8; ++i) s += sQBp[i * 64 + tid];
        sQB[tid] = s;
    }
    __syncthreads();

    // ---- Stage D: h1 = relu(K @ Weff + qbias) ----
    // warp = (token-group of 64, h-block of 16). lane-token K loads (conflict-free),
    // warp-uniform W loads (broadcast). 2 tokens x 16 h per thread.
    {
        int w = tid >> 5, lane = tid & 31;
        int tg = w >> 2;            // 0..3 : tokens [tg*64, tg*64+64)
        int h0 = (w & 3) * 16;      // 4 h-blocks of 16
        int t0 = tg * 64 + lane;
        int t1 = t0 + 32;
        ull acc0[16], acc1[16];
        #pragma unroll
        for (int j = 0; j < 16; ++j) { acc0[j] = 0ull; acc1[j] = 0ull; }

        const ull* kA = (const ull*)sK + t0 * SK_ULL;   // t>=200 reads stale smem; discarded
        const ull* kB = (const ull*)sK + t1 * SK_ULL;
        const ulonglong2* wbase = (const ulonglong2*)(sWp + h0);
        #pragma unroll 4
        for (int ep = 0; ep < NE / 2; ++ep) {
            ull ka = kA[ep];
            ull kb = kB[ep];
            const ulonglong2* wp = wbase + ep * 32;   // 64 ull per ep row
            #pragma unroll
            for (int j = 0; j < 8; ++j) {
                ulonglong2 wv = wp[j];
                acc0[2 * j]     = fma2(ka, wv.x, acc0[2 * j]);
                acc0[2 * j + 1] = fma2(ka, wv.y, acc0[2 * j + 1]);
                acc1[2 * j]     = fma2(kb, wv.x, acc1[2 * j]);
                acc1[2 * j + 1] = fma2(kb, wv.y, acc1[2 * j + 1]);
            }
        }
        if (t0 < NT) {
            float* dst = sH + t0 * SH_STRIDE + h0;
            #pragma unroll
            for (int j = 0; j < 16; ++j) {
                float2 v = unpack2(acc0[j]);
                dst[j] = fmaxf(v.x + v.y + sQB[h0 + j], 0.f);
            }
        }
        if (t1 < NT) {
            float* dst = sH + t1 * SH_STRIDE + h0;
            #pragma unroll
            for (int j = 0; j < 16; ++j) {
                float2 v = unpack2(acc1[j]);
                dst[j] = fmaxf(v.x + v.y + sQB[h0 + j], 0.f);
            }
        }
    }
    __syncthreads();

    // ---- Stage E: scores. warp = token stream, lane = H2 unit ----
    {
        int warp = tid >> 5, lane = tid & 31;
        float w3v = sW3v[lane];
        float b2v = sB2[lane];
        float b3v = b3[0];
        const ull* wrow = (const ull*)(sW2t + lane * SW2T_STRIDE);
        for (int t = warp; t < NT; t += 16) {
            const ull* hrow = (const ull*)(sH + t * SH_STRIDE);
            ull a2 = 0ull;
            #pragma unroll
            for (int j = 0; j < 32; ++j)
                a2 = fma2(hrow[j], wrow[j], a2);
            float2 v = unpack2(a2);
            float h2v = fmaxf(v.x + v.y + b2v, 0.f);
            float contrib = h2v * w3v;
            #pragma unroll
            for (int o = 16; o; o >>= 1)
                contrib += __shfl_xor_sync(0xffffffffu, contrib, o);
            if (lane == 0) {
                float sc = contrib + b3v;
                sS[t] = (keys_id[b * NT + t] != 0) ? sc : NEG_INF;
            }
        }
    }
    __syncthreads();

    // ---- Stage F: masked softmax over T ----
    {
        float v = (tid < NT) ? sS[tid] : -3.0e38f;
        float m = v;
        #pragma unroll
        for (int o = 16; o; o >>= 1) m = fmaxf(m, __shfl_xor_sync(0xffffffffu, m, o));
        if ((tid & 31) == 0) sRed[tid >> 5] = m;
        __syncthreads();
        float mx = sRed[0];
        #pragma unroll
        for (int i = 1; i < 16; ++i) mx = fmaxf(mx, sRed[i]);
        float p = (tid < NT) ? __expf(v - mx) : 0.f;
        float s = p;
        #pragma unroll
        for (int o = 16; o; o >>= 1) s += __shfl_xor_sync(0xffffffffu, s, o);
        __syncthreads();                  // sRed reuse barrier
        if ((tid & 31) == 0) sRed[tid >> 5] = s;
        __syncthreads();
        float tot = 0.f;
        #pragma unroll
        for (int i = 0; i < 16; ++i) tot += sRed[i];
        if (tid < NT) sS[tid] = p / tot;
    }
    __syncthreads();

    // ---- Stage G: out[e] = (1/T) * sum_t w[t] * K[t][e] ----
    {
        int pr = tid & 63;      // e-pair index
        int seg = tid >> 6;     // 8 t-segments of 25
        ull a2 = 0ull;
        int t0 = seg * 25;
        #pragma unroll 5
        for (int t = t0; t < t0 + 25; ++t) {
            ull wv = pack2(sS[t]);
            const ull* krow = (const ull*)sK + t * SK_ULL;
            a2 = fma2(wv, krow[pr], a2);
        }
        float2 v = unpack2(a2);
        sPool[seg * 128 + 2 * pr]     = v.x;
        sPool[seg * 128 + 2 * pr + 1] = v.y;
    }
    __syncthreads();
    if (tid < NE) {
        float r = 0.f;
        #pragma unroll
        for (int i = 0; i < 8; ++i) r += sPool[i * 128 + tid];
        out[b * NE + tid] = r * (1.0f / NT);
    }
}

extern "C" void kernel_launch(void* const* d_in, const int* in_sizes, int n_in,
                              void* d_out, int out_size) {
    const float* queries = (const float*)d_in[0];
    const float* keys    = (const float*)d_in[1];
    const int*   keys_id = (const int*)  d_in[2];
    const float* W1      = (const float*)d_in[3];
    const float* b1      = (const float*)d_in[4];
    const float* W2      = (const float*)d_in[5];
    const float* b2      = (const float*)d_in[6];
    const float* W3      = (const float*)d_in[7];
    const float* b3      = (const float*)d_in[8];
    float* out = (float*)d_out;

    cudaFuncSetAttribute(attn_kernel,
                         cudaFuncAttributeMaxDynamicSharedMemorySize, SMEM_TOTAL);
    attn_kernel<<<NB, 512, SMEM_TOTAL>>>(queries, keys, keys_id,
                                         W1, b1, W2, b2, W3, b3, out);
}

// round 12
// speedup vs baseline: 1.2834x; 1.2606x over previous
#include <cuda_runtime.h>
#include <cuda_bf16.h>
#include <cstdint>

typedef unsigned long long ull;

#define NB 2048
#define NT 200
#define NE 128
#define NH1 64
#define NH2 32
#define NEG_INF (-4294967295.0f)

// K-tile row stride: 136 bf16 = 68 words (odd multiple of 4 -> conflict-free frags)
#define KW 68

// ---- SMEM layout (bytes) ----
#define OFF_KHI  0        // 208 x 136 bf16 = 56576
#define OFF_KLO  56576    // 56576
#define OFF_WHI  113152   // 64 x 136 bf16 = 17408
#define OFF_WLO  130560   // 17408
#define OFF_SH   147968   // 200 x 33 ull = 52800
#define OFF_W2P  200768   // 32 x 33 ull = 8448
#define OFF_SQ   209216   // 512
#define OFF_SQBP 209728   // 2048
#define OFF_SQB  211776   // 256
#define OFF_SS   212032   // 832
#define OFF_SB2  212864   // 128
#define OFF_SW3  212992   // 128
#define OFF_SRED 213120   // 128
#define OFF_SPOOL 213248  // 4096
#define SMEM_TOTAL 217344

__device__ __forceinline__ ull fma2(ull a, ull b, ull c) {
    ull d;
    asm("fma.rn.f32x2 %0, %1, %2, %3;" : "=l"(d) : "l"(a), "l"(b), "l"(c));
    return d;
}
__device__ __forceinline__ float2 unpack2(ull v) {
    float2 r;
    asm("mov.b64 {%0, %1}, %2;" : "=f"(r.x), "=f"(r.y) : "l"(v));
    return r;
}
__device__ __forceinline__ void mma16816(float* c, const uint32_t* a, const uint32_t* b) {
    asm volatile("mma.sync.aligned.m16n8k16.row.col.f32.bf16.bf16.f32 "
        "{%0,%1,%2,%3}, {%4,%5,%6,%7}, {%8,%9}, {%0,%1,%2,%3};"
        : "+f"(c[0]), "+f"(c[1]), "+f"(c[2]), "+f"(c[3])
        : "r"(a[0]), "r"(a[1]), "r"(a[2]), "r"(a[3]), "r"(b[0]), "r"(b[1]));
}

__global__ __launch_bounds__(512, 1)
void attn_kernel(const float* __restrict__ queries, const float* __restrict__ keys,
                 const int* __restrict__ keys_id, const float* __restrict__ W1,
                 const float* __restrict__ b1, const float* __restrict__ W2,
                 const float* __restrict__ b2, const float* __restrict__ W3,
                 const float* __restrict__ b3, float* __restrict__ out)
{
    extern __shared__ char smem[];
    const int tid = threadIdx.x;
    const int wid = tid >> 5;
    const int lane = tid & 31;
    const int b = blockIdx.x;

    uint32_t* KHI = (uint32_t*)(smem + OFF_KHI);
    uint32_t* KLO = (uint32_t*)(smem + OFF_KLO);
    uint32_t* WHI = (uint32_t*)(smem + OFF_WHI);
    uint32_t* WLO = (uint32_t*)(smem + OFF_WLO);
    ull*   sHull = (ull*)(smem + OFF_SH);
    ull*   w2p   = (ull*)(smem + OFF_W2P);
    float* sQ    = (float*)(smem + OFF_SQ);
    float* sQBp  = (float*)(smem + OFF_SQBP);
    float* sQB   = (float*)(smem + OFF_SQB);
    float* sS    = (float*)(smem + OFF_SS);
    float* sB2   = (float*)(smem + OFF_SB2);
    float* sW3v  = (float*)(smem + OFF_SW3);
    float* sRed  = (float*)(smem + OFF_SRED);
    float* sPool = (float*)(smem + OFF_SPOOL);

    // ---- Stage A0: small loads ----
    if (tid < NE) sQ[tid] = queries[b * NE + tid];
    for (int i = tid; i < 1024; i += 512) {     // W2 pair pack
        int hp = i >> 5, k = i & 31;
        float a = W2[(2 * hp) * NH2 + k];
        float c = W2[(2 * hp + 1) * NH2 + k];
        ull v; asm("mov.b64 %0, {%1,%2};" : "=l"(v) : "f"(a), "f"(c));
        w2p[k * 33 + hp] = v;
    }
    if (tid < NH2) { sB2[tid] = b2[tid]; sW3v[tid] = W3[tid]; }
    // zero K-tile tail rows 200..207 (read by last m-tile, results discarded)
    for (int i = tid; i < 8 * KW; i += 512) {
        KHI[200 * KW + i] = 0; KLO[200 * KW + i] = 0;
    }
    __syncthreads();   // sQ visible

    // ---- Stage A1: K -> bf16 hi/lo tiles [t][e], stride 68 words ----
    {
        const float2* gKf = (const float2*)(keys + (size_t)b * NT * NE);
        #pragma unroll 5
        for (int idx = tid; idx < NT * 64; idx += 512) {
            int t = idx >> 6, pe = idx & 63;
            float2 kv = gKf[idx];
            __nv_bfloat16 hx = __float2bfloat16_rn(kv.x);
            __nv_bfloat16 hy = __float2bfloat16_rn(kv.y);
            __nv_bfloat162 hp2; hp2.x = hx; hp2.y = hy;
            __nv_bfloat162 lp2;
            lp2.x = __float2bfloat16_rn(kv.x - __bfloat162float(hx));
            lp2.y = __float2bfloat16_rn(kv.y - __bfloat162float(hy));
            KHI[t * KW + pe] = *(uint32_t*)&hp2;
            KLO[t * KW + pe] = *(uint32_t*)&lp2;
        }
    }
    // ---- Stage A2: Weff = (W1b - W1c) + q .* W1d -> bf16 hi/lo, [h][e] ----
    for (int i = tid; i < NE * NH1; i += 512) {
        int e = i >> 6, h = i & 63;
        float wb = W1[(NE + e) * NH1 + h];
        float wc = W1[(2 * NE + e) * NH1 + h];
        float wd = W1[(3 * NE + e) * NH1 + h];
        float w = wb - wc + sQ[e] * wd;
        __nv_bfloat16 hi = __float2bfloat16_rn(w);
        float lo = w - __bfloat162float(hi);
        *(unsigned short*)((char*)WHI + h * 272 + e * 2) = __bfloat16_as_ushort(hi);
        *(unsigned short*)((char*)WLO + h * 272 + e * 2) =
            __bfloat16_as_ushort(__float2bfloat16_rn(lo));
    }
    // qbias partials: qb[h] = b1[h] + sum_e q[e]*(W1a + W1c)[e][h]
    {
        int h = tid & 63, seg = tid >> 6;   // 8 segments of 16 e
        float p = 0.f;
        int e0 = seg * 16;
        #pragma unroll 4
        for (int e = e0; e < e0 + 16; ++e)
            p += sQ[e] * (W1[e * NH1 + h] + W1[(2 * NE + e) * NH1 + h]);
        sQBp[seg * 64 + h] = p;
    }
    __syncthreads();   // tiles + sQBp visible

    // ---- Stage D: h1 = relu(K @ Weff + qbias) via mma.sync bf16 3-term ----
    float acc[8][4];
    #pragma unroll
    for (int nt = 0; nt < 8; ++nt)
        #pragma unroll
        for (int j = 0; j < 4; ++j) acc[nt][j] = 0.f;

    const int g = lane >> 2, kwid = lane & 3;
    if (wid < 13) {
        const int r0 = (wid * 16 + g) * KW;
        const int r1 = r0 + 8 * KW;
        #pragma unroll 2
        for (int ks = 0; ks < 8; ++ks) {
            int kc = ks * 8 + kwid;
            uint32_t ah[4], al[4];
            ah[0] = KHI[r0 + kc]; ah[1] = KHI[r1 + kc];
            ah[2] = KHI[r0 + kc + 4]; ah[3] = KHI[r1 + kc + 4];
            al[0] = KLO[r0 + kc]; al[1] = KLO[r1 + kc];
            al[2] = KLO[r0 + kc + 4]; al[3] = KLO[r1 + kc + 4];
            #pragma unroll
            for (int nt = 0; nt < 8; ++nt) {
                int rb = (nt * 8 + g) * KW + kc;
                uint32_t bh[2], bl[2];
                bh[0] = WHI[rb]; bh[1] = WHI[rb + 4];
                bl[0] = WLO[rb]; bl[1] = WLO[rb + 4];
                mma16816(acc[nt], ah, bh);
                mma16816(acc[nt], al, bh);
                mma16816(acc[nt], ah, bl);
            }
        }
    } else if (tid >= 416 && tid < 480) {   // warps 13-14: qbias reduce
        int h = tid - 416;
        float s = b1[h];
        #pragma unroll
        for (int i = 0; i < 8; ++i) s += sQBp[i * 64 + h];
        sQB[h] = s;
    }
    __syncthreads();   // sQB ready; all mma done (register results)

    // ---- epilogue: D + qbias, relu, pack pairs -> sH [t][33 ull] ----
    if (wid < 13) {
        int token0 = wid * 16 + g;       // < 200 always
        int token1 = token0 + 8;
        #pragma unroll
        for (int nt = 0; nt < 8; ++nt) {
            int h = nt * 8 + kwid * 2;
            float qa = sQB[h], qc = sQB[h + 1];
            int hp = nt * 4 + kwid;
            {
                float x = fmaxf(acc[nt][0] + qa, 0.f);
                float y = fmaxf(acc[nt][1] + qc, 0.f);
                ull v; asm("mov.b64 %0, {%1,%2};" : "=l"(v) : "f"(x), "f"(y));
                sHull[token0 * 33 + hp] = v;
            }
            if (token1 < NT) {
                float x = fmaxf(acc[nt][2] + qa, 0.f);
                float y = fmaxf(acc[nt][3] + qc, 0.f);
                ull v; asm("mov.b64 %0, {%1,%2};" : "=l"(v) : "f"(x), "f"(y));
                sHull[token1 * 33 + hp] = v;
            }
        }
    }
    __syncthreads();

    // ---- Stage E: scores. warp = token stream, lane = H2 unit ----
    {
        ull wreg[32];
        #pragma unroll
        for (int j = 0; j < 32; ++j) wreg[j] = w2p[lane * 33 + j];
        float w3v = sW3v[lane];
        float b2v = sB2[lane];
        float b3v = b3[0];
        for (int t = wid; t < NT; t += 16) {
            const ull* hrow = sHull + t * 33;
            ull a0 = 0ull, a1 = 0ull;
            #pragma unroll
            for (int j = 0; j < 16; ++j) {
                a0 = fma2(hrow[2 * j],     wreg[2 * j],     a0);
                a1 = fma2(hrow[2 * j + 1], wreg[2 * j + 1], a1);
            }
            float2 v0 = unpack2(a0), v1 = unpack2(a1);
            float h2v = fmaxf(v0.x + v0.y + v1.x + v1.y + b2v, 0.f);
            float contrib = h2v * w3v;
            #pragma unroll
            for (int o = 16; o; o >>= 1)
                contrib += __shfl_xor_sync(0xffffffffu, contrib, o);
            if (lane == 0) {
                float sc = contrib + b3v;
                sS[t] = (keys_id[b * NT + t] != 0) ? sc : NEG_INF;
            }
        }
    }
    __syncthreads();

    // ---- Stage F: masked softmax over T ----
    {
        float v = (tid < NT) ? sS[tid] : -3.0e38f;
        float m = v;
        #pragma unroll
        for (int o = 16; o; o >>= 1) m = fmaxf(m, __shfl_xor_sync(0xffffffffu, m, o));
        if (lane == 0) sRed[wid] = m;
        __syncthreads();
        float mx = sRed[0];
        #pragma unroll
        for (int i = 1; i < 16; ++i) mx = fmaxf(mx, sRed[i]);
        float p = (tid < NT) ? __expf(v - mx) : 0.f;
        float s = p;
        #pragma unroll
        for (int o = 16; o; o >>= 1) s += __shfl_xor_sync(0xffffffffu, s, o);
        __syncthreads();
        if (lane == 0) sRed[wid] = s;
        __syncthreads();
        float tot = 0.f;
        #pragma unroll
        for (int i = 0; i < 16; ++i) tot += sRed[i];
        if (tid < NT) sS[tid] = p / tot;
    }
    __syncthreads();

    // ---- Stage G: pool. K reconstructed from bf16 hi+lo (err ~2^-17) ----
    {
        int pr = tid & 63;      // e-pair index
        int seg = tid >> 6;     // 8 t-segments of 25
        float ax = 0.f, ay = 0.f;
        int t0 = seg * 25;
        #pragma unroll 5
        for (int t = t0; t < t0 + 25; ++t) {
            float wv = sS[t];
            __nv_bfloat162 h2 = *(__nv_bfloat162*)&KHI[t * KW + pr];
            __nv_bfloat162 l2 = *(__nv_bfloat162*)&KLO[t * KW + pr];
            float2 fh = __bfloat1622float2(h2);
            float2 fl = __bfloat1622float2(l2);
            ax = fmaf(wv, fh.x + fl.x, ax);
            ay = fmaf(wv, fh.y + fl.y, ay);
        }
        sPool[seg * 128 + 2 * pr]     = ax;
        sPool[seg * 128 + 2 * pr + 1] = ay;
    }
    __syncthreads();
    if (tid < NE) {
        float r = 0.f;
        #pragma unroll
        for (int i = 0; i < 8; ++i) r += sPool[i * 128 + tid];
        out[b * NE + tid] = r * (1.0f / NT);
    }
}

extern "C" void kernel_launch(void* const* d_in, const int* in_sizes, int n_in,
                              void* d_out, int out_size) {
    const float* queries = (const float*)d_in[0];
    const float* keys    = (const float*)d_in[1];
    const int*   keys_id = (const int*)  d_in[2];
    const float* W1      = (const float*)d_in[3];
    const float* b1      = (const float*)d_in[4];
    const float* W2      = (const float*)d_in[5];
    const float* b2      = (const float*)d_in[6];
    const float* W3      = (const float*)d_in[7];
    const float* b3      = (const float*)d_in[8];
    float* out = (float*)d_out;

    cudaFuncSetAttribute(attn_kernel,
                         cudaFuncAttributeMaxDynamicSharedMemorySize, SMEM_TOTAL);
    attn_kernel<<<NB, 512, SMEM_TOTAL>>>(queries, keys, keys_id,
                                         W1, b1, W2, b2, W3, b3, out);
}

// round 13
// speedup vs baseline: 1.8849x; 1.4687x over previous
#include <cuda_runtime.h>
#include <cuda_bf16.h>
#include <cstdint>

typedef unsigned long long ull;

#define NB 2048
#define NT 200
#define NE 128
#define NH1 64
#define NH2 32
#define NEG_INF (-4294967295.0f)

// W-tile row stride in 32-bit words (64 e-pairs + 4 pad -> conflict-free frags)
#define KW 68

// ---- SMEM layout (bytes), total 102144 -> 2 CTAs/SM ----
#define OFF_WHI  0        // 64 x 68 words = 17408
#define OFF_WLO  17408    // 17408
#define OFF_SH   34816    // 200 x 33 ull = 52800
#define OFF_W2P  87616    // 32 x 33 ull = 8448
#define OFF_SQ   96064    // 512
#define OFF_SQBP 96576    // 2048
#define OFF_SQB  98624    // 256
#define OFF_SS   98880    // 832
#define OFF_SB2  99712    // 128
#define OFF_SW3  99840    // 128
#define OFF_SRED 99968    // 128
#define OFF_SPOOL 100096  // 4 x 128 x 4 = 2048
#define SMEM_TOTAL 102144

__device__ __forceinline__ ull fma2(ull a, ull b, ull c) {
    ull d;
    asm("fma.rn.f32x2 %0, %1, %2, %3;" : "=l"(d) : "l"(a), "l"(b), "l"(c));
    return d;
}
__device__ __forceinline__ float2 unpack2(ull v) {
    float2 r;
    asm("mov.b64 {%0, %1}, %2;" : "=f"(r.x), "=f"(r.y) : "l"(v));
    return r;
}
__device__ __forceinline__ void mma16816(float* c, const uint32_t* a, const uint32_t* b) {
    asm volatile("mma.sync.aligned.m16n8k16.row.col.f32.bf16.bf16.f32 "
        "{%0,%1,%2,%3}, {%4,%5,%6,%7}, {%8,%9}, {%0,%1,%2,%3};"
        : "+f"(c[0]), "+f"(c[1]), "+f"(c[2]), "+f"(c[3])
        : "r"(a[0]), "r"(a[1]), "r"(a[2]), "r"(a[3]), "r"(b[0]), "r"(b[1]));
}
// float2 -> packed bf16x2 hi, and packed bf16x2 of the residual (lo)
__device__ __forceinline__ void cvt_hilo(float2 v, uint32_t& hi, uint32_t& lo) {
    __nv_bfloat16 hx = __float2bfloat16_rn(v.x);
    __nv_bfloat16 hy = __float2bfloat16_rn(v.y);
    __nv_bfloat162 h2; h2.x = hx; h2.y = hy;
    __nv_bfloat162 l2;
    l2.x = __float2bfloat16_rn(v.x - __bfloat162float(hx));
    l2.y = __float2bfloat16_rn(v.y - __bfloat162float(hy));
    hi = *(uint32_t*)&h2;
    lo = *(uint32_t*)&l2;
}

__global__ __launch_bounds__(256, 2)
void attn_kernel(const float* __restrict__ queries, const float* __restrict__ keys,
                 const int* __restrict__ keys_id, const float* __restrict__ W1,
                 const float* __restrict__ b1, const float* __restrict__ W2,
                 const float* __restrict__ b2, const float* __restrict__ W3,
                 const float* __restrict__ b3, float* __restrict__ out)
{
    extern __shared__ char smem[];
    const int tid = threadIdx.x;
    const int wid = tid >> 5;
    const int lane = tid & 31;
    const int b = blockIdx.x;

    uint32_t* WHI = (uint32_t*)(smem + OFF_WHI);
    uint32_t* WLO = (uint32_t*)(smem + OFF_WLO);
    ull*   sHull = (ull*)(smem + OFF_SH);
    ull*   w2p   = (ull*)(smem + OFF_W2P);
    float* sQ    = (float*)(smem + OFF_SQ);
    float* sQBp  = (float*)(smem + OFF_SQBP);
    float* sQB   = (float*)(smem + OFF_SQB);
    float* sS    = (float*)(smem + OFF_SS);
    float* sB2   = (float*)(smem + OFF_SB2);
    float* sW3v  = (float*)(smem + OFF_SW3);
    float* sRed  = (float*)(smem + OFF_SRED);
    float* sPool = (float*)(smem + OFF_SPOOL);

    // ---- Stage A: small loads ----
    if (tid < NE) sQ[tid] = queries[b * NE + tid];
    #pragma unroll
    for (int i = tid; i < 1024; i += 256) {     // W2 pair pack
        int hp = i >> 5, k = i & 31;
        float a = W2[(2 * hp) * NH2 + k];
        float c = W2[(2 * hp + 1) * NH2 + k];
        ull v; asm("mov.b64 %0, {%1,%2};" : "=l"(v) : "f"(a), "f"(c));
        w2p[k * 33 + hp] = v;
    }
    if (tid < NH2) { sB2[tid] = b2[tid]; sW3v[tid] = W3[tid]; }
    __syncthreads();   // sQ visible

    // ---- Stage B: Weff = (W1b - W1c) + q .* W1d -> bf16 hi/lo, [h][e] ----
    #pragma unroll 4
    for (int i = tid; i < NE * NH1; i += 256) {
        int e = i >> 6, h = i & 63;
        float wb = W1[(NE + e) * NH1 + h];
        float wc = W1[(2 * NE + e) * NH1 + h];
        float wd = W1[(3 * NE + e) * NH1 + h];
        float w = wb - wc + sQ[e] * wd;
        __nv_bfloat16 hi = __float2bfloat16_rn(w);
        float lo = w - __bfloat162float(hi);
        *(unsigned short*)((char*)WHI + h * 272 + e * 2) = __bfloat16_as_ushort(hi);
        *(unsigned short*)((char*)WLO + h * 272 + e * 2) =
            __bfloat16_as_ushort(__float2bfloat16_rn(lo));
    }
    // qbias partials: qb[h] = b1[h] + sum_e q[e]*(W1a + W1c)[e][h]
    #pragma unroll
    for (int i = tid; i < 512; i += 256) {
        int h = i & 63, seg = i >> 6;   // 8 segments of 16 e
        float p = 0.f;
        int e0 = seg * 16;
        #pragma unroll 4
        for (int e = e0; e < e0 + 16; ++e)
            p += sQ[e] * (W1[e * NH1 + h] + W1[(2 * NE + e) * NH1 + h]);
        sQBp[seg * 64 + h] = p;
    }
    __syncthreads();
    if (tid < NH1) {
        float s = b1[tid];
        #pragma unroll
        for (int i = 0; i < 8; ++i) s += sQBp[i * 64 + tid];
        sQB[tid] = s;
    }
    __syncthreads();   // W tiles + sQB visible

    // ---- Stage D: h1 = relu(K @ Weff + qbias). A-frags direct from GMEM ----
    // warp w handles m-tiles w, w+8 (13 tiles of 16 tokens). 3-term bf16 split.
    {
        const int g = lane >> 2, kwid = lane & 3;
        const float* gK = keys + (size_t)b * NT * NE;
        for (int m = wid; m < 13; m += 8) {
            int r0 = m * 16 + g;                  // always <= 199
            int r1 = r0 + 8;
            int r1c = (r1 < NT) ? r1 : (NT - 1);  // clamp; results discarded
            const float* krow0 = gK + r0 * NE;
            const float* krow1 = gK + r1c * NE;

            float acc[8][4];
            #pragma unroll
            for (int nt = 0; nt < 8; ++nt)
                #pragma unroll
                for (int j = 0; j < 4; ++j) acc[nt][j] = 0.f;

            #pragma unroll
            for (int ks = 0; ks < 8; ++ks) {
                int c0 = ks * 16 + kwid * 2;
                float2 f00 = *(const float2*)(krow0 + c0);
                float2 f10 = *(const float2*)(krow1 + c0);
                float2 f01 = *(const float2*)(krow0 + c0 + 8);
                float2 f11 = *(const float2*)(krow1 + c0 + 8);
                uint32_t ah[4], al[4];
                cvt_hilo(f00, ah[0], al[0]);
                cvt_hilo(f10, ah[1], al[1]);
                cvt_hilo(f01, ah[2], al[2]);
                cvt_hilo(f11, ah[3], al[3]);
                int kc = ks * 8 + kwid;
                #pragma unroll
                for (int nt = 0; nt < 8; ++nt) {
                    int rb = (nt * 8 + g) * KW + kc;
                    uint32_t bh[2], bl[2];
                    bh[0] = WHI[rb]; bh[1] = WHI[rb + 4];
                    bl[0] = WLO[rb]; bl[1] = WLO[rb + 4];
                    mma16816(acc[nt], ah, bh);
                    mma16816(acc[nt], al, bh);
                    mma16816(acc[nt], ah, bl);
                }
            }
            // epilogue: relu(D + qbias) pairs -> sH [t][33 ull]
            #pragma unroll
            for (int nt = 0; nt < 8; ++nt) {
                int h = nt * 8 + kwid * 2;
                float qa = sQB[h], qc = sQB[h + 1];
                int hp = nt * 4 + kwid;
                {
                    float x = fmaxf(acc[nt][0] + qa, 0.f);
                    float y = fmaxf(acc[nt][1] + qc, 0.f);
                    ull v; asm("mov.b64 %0, {%1,%2};" : "=l"(v) : "f"(x), "f"(y));
                    sHull[r0 * 33 + hp] = v;
                }
                if (r1 < NT) {
                    float x = fmaxf(acc[nt][2] + qa, 0.f);
                    float y = fmaxf(acc[nt][3] + qc, 0.f);
                    ull v; asm("mov.b64 %0, {%1,%2};" : "=l"(v) : "f"(x), "f"(y));
                    sHull[r1 * 33 + hp] = v;
                }
            }
        }
    }
    __syncthreads();

    // ---- Stage E: scores. warp = token stream, lane = H2 unit ----
    {
        ull wreg[32];
        #pragma unroll
        for (int j = 0; j < 32; ++j) wreg[j] = w2p[lane * 33 + j];
        float w3v = sW3v[lane];
        float b2v = sB2[lane];
        float b3v = b3[0];
        for (int t = wid; t < NT; t += 8) {
            const ull* hrow = sHull + t * 33;
            ull a0 = 0ull, a1 = 0ull;
            #pragma unroll
            for (int j = 0; j < 16; ++j) {
                a0 = fma2(hrow[2 * j],     wreg[2 * j],     a0);
                a1 = fma2(hrow[2 * j + 1], wreg[2 * j + 1], a1);
            }
            float2 v0 = unpack2(a0), v1 = unpack2(a1);
            float h2v = fmaxf(v0.x + v0.y + v1.x + v1.y + b2v, 0.f);
            float contrib = h2v * w3v;
            #pragma unroll
            for (int o = 16; o; o >>= 1)
                contrib += __shfl_xor_sync(0xffffffffu, contrib, o);
            if (lane == 0) {
                float sc = contrib + b3v;
                sS[t] = (keys_id[b * NT + t] != 0) ? sc : NEG_INF;
            }
        }
    }
    __syncthreads();

    // ---- Stage F: masked softmax over T ----
    {
        float v = (tid < NT) ? sS[tid] : -3.0e38f;
        float m = v;
        #pragma unroll
        for (int o = 16; o; o >>= 1) m = fmaxf(m, __shfl_xor_sync(0xffffffffu, m, o));
        if (lane == 0) sRed[wid] = m;
        __syncthreads();
        float mx = sRed[0];
        #pragma unroll
        for (int i = 1; i < 8; ++i) mx = fmaxf(mx, sRed[i]);
        float p = (tid < NT) ? __expf(v - mx) : 0.f;
        float s = p;
        #pragma unroll
        for (int o = 16; o; o >>= 1) s += __shfl_xor_sync(0xffffffffu, s, o);
        __syncthreads();
        if (lane == 0) sRed[wid] = s;
        __syncthreads();
        float tot = 0.f;
        #pragma unroll
        for (int i = 0; i < 8; ++i) tot += sRed[i];
        if (tid < NT) sS[tid] = p / tot;
        // handle tokens 200..255 handled above; nothing else
    }
    __syncthreads();

    // ---- Stage G: out[e] = (1/T) * sum_t w[t] * K[t][e]  (keys from L2, fp32) ----
    {
        int pr = tid & 63;      // e-pair index
        int seg = tid >> 6;     // 4 t-segments of 50
        const ull* gK2 = (const ull*)(keys + (size_t)b * NT * NE);
        float ax = 0.f, ay = 0.f;
        int t0 = seg * 50;
        #pragma unroll 5
        for (int t = t0; t < t0 + 50; ++t) {
            float wv = sS[t];
            float2 kv = unpack2(gK2[t * 64 + pr]);
            ax = fmaf(wv, kv.x, ax);
            ay = fmaf(wv, kv.y, ay);
        }
        sPool[seg * 128 + 2 * pr]     = ax;
        sPool[seg * 128 + 2 * pr + 1] = ay;
    }
    __syncthreads();
    if (tid < NE) {
        float r = sPool[tid] + sPool[128 + tid] + sPool[256 + tid] + sPool[384 + tid];
        out[b * NE + tid] = r * (1.0f / NT);
    }
}

extern "C" void kernel_launch(void* const* d_in, const int* in_sizes, int n_in,
                              void* d_out, int out_size) {
    const float* queries = (const float*)d_in[0];
    const float* keys    = (const float*)d_in[1];
    const int*   keys_id = (const int*)  d_in[2];
    const float* W1      = (const float*)d_in[3];
    const float* b1      = (const float*)d_in[4];
    const float* W2      = (const float*)d_in[5];
    const float* b2      = (const float*)d_in[6];
    const float* W3      = (const float*)d_in[7];
    const float* b3      = (const float*)d_in[8];
    float* out = (float*)d_out;

    cudaFuncSetAttribute(attn_kernel,
                         cudaFuncAttributeMaxDynamicSharedMemorySize, SMEM_TOTAL);
    attn_kernel<<<NB, 256, SMEM_TOTAL>>>(queries, keys, keys_id,
                                         W1, b1, W2, b2, W3, b3, out);
}

// round 15
// speedup vs baseline: 2.8826x; 1.5293x over previous
#include <cuda_runtime.h>
#include <cuda_bf16.h>
#include <cstdint>

typedef unsigned long long ull;

#define NB 2048
#define NT 200
#define NE 128
#define NH1 64
#define NH2 32
#define NEG_INF (-4294967295.0f)

// Weff tile row stride in words (64 e-pair words + 4 pad)
#define KW 68
// h1 bf16-pair tile row stride in words (32 pair words + 4 pad; 36 -> 4g+kwid banks)
#define HSTR 36
// W2 frag tile row stride in words (32 n + 8 pad; 40 -> 8kwid+g banks)
#define W2STR 40

// ---- SMEM layout (bytes), total 111040 -> 2 CTAs/SM ----
#define OFF_WHI  0        // 64 x 68 x 4 = 17408
#define OFF_WLO  17408    // 17408
#define OFF_HH   34816    // 208 x 36 x 4 = 29952 (h1 hi pairs)
#define OFF_HL   64768    // 29952 (h1 lo pairs)
#define OFF_W2H  94720    // 32 x 40 x 4 = 5120
#define OFF_W2L  99840    // 5120
#define OFF_SQ   104960   // 512
#define OFF_SQBP 105472   // 2048
#define OFF_SQB  107520   // 256
#define OFF_SS   107776   // 832
#define OFF_SB2  108608   // 128
#define OFF_SW3  108736   // 128
#define OFF_SRED 108864   // 128
#define OFF_SPOOL 108992  // 2048
#define SMEM_TOTAL 111040

__device__ __forceinline__ float2 unpack2(ull v) {
    float2 r;
    asm("mov.b64 {%0, %1}, %2;" : "=f"(r.x), "=f"(r.y) : "l"(v));
    return r;
}
__device__ __forceinline__ void mma16816(float* c, const uint32_t* a, const uint32_t* b) {
    asm volatile("mma.sync.aligned.m16n8k16.row.col.f32.bf16.bf16.f32 "
        "{%0,%1,%2,%3}, {%4,%5,%6,%7}, {%8,%9}, {%0,%1,%2,%3};"
        : "+f"(c[0]), "+f"(c[1]), "+f"(c[2]), "+f"(c[3])
        : "r"(a[0]), "r"(a[1]), "r"(a[2]), "r"(a[3]), "r"(b[0]), "r"(b[1]));
}
// (v.x, v.y) -> packed bf16x2 hi (x in low half) and packed bf16x2 residual lo
__device__ __forceinline__ void cvt_hilo2(float2 v, uint32_t& hi, uint32_t& lo) {
    uint32_t h;
    asm("cvt.rn.bf16x2.f32 %0, %1, %2;" : "=r"(h) : "f"(v.y), "f"(v.x));
    float hx = __uint_as_float(h << 16);
    float hy = __uint_as_float(h & 0xffff0000u);
    float lx = v.x - hx, ly = v.y - hy;
    uint32_t l;
    asm("cvt.rn.bf16x2.f32 %0, %1, %2;" : "=r"(l) : "f"(ly), "f"(lx));
    hi = h; lo = l;
}

__global__ __launch_bounds__(256, 2)
void attn_kernel(const float* __restrict__ queries, const float* __restrict__ keys,
                 const int* __restrict__ keys_id, const float* __restrict__ W1,
                 const float* __restrict__ b1, const float* __restrict__ W2,
                 const float* __restrict__ b2, const float* __restrict__ W3,
                 const float* __restrict__ b3, float* __restrict__ out)
{
    extern __shared__ char smem[];
    const int tid = threadIdx.x;
    const int wid = tid >> 5;
    const int lane = tid & 31;
    const int b = blockIdx.x;

    uint32_t* WHI = (uint32_t*)(smem + OFF_WHI);
    uint32_t* WLO = (uint32_t*)(smem + OFF_WLO);
    uint32_t* HH  = (uint32_t*)(smem + OFF_HH);
    uint32_t* HL  = (uint32_t*)(smem + OFF_HL);
    uint32_t* W2H = (uint32_t*)(smem + OFF_W2H);
    uint32_t* W2L = (uint32_t*)(smem + OFF_W2L);
    float* sQ    = (float*)(smem + OFF_SQ);
    float* sQBp  = (float*)(smem + OFF_SQBP);
    float* sQB   = (float*)(smem + OFF_SQB);
    float* sS    = (float*)(smem + OFF_SS);
    float* sB2   = (float*)(smem + OFF_SB2);
    float* sW3v  = (float*)(smem + OFF_SW3);
    float* sRed  = (float*)(smem + OFF_SRED);
    float* sPool = (float*)(smem + OFF_SPOOL);

    // ---- Stage A: small loads; W2 frag pack (bf16 hi/lo) ----
    if (tid < NE) sQ[tid] = queries[b * NE + tid];
    #pragma unroll
    for (int i = tid; i < 1024; i += 256) {
        int kp = i >> 5, n = i & 31;    // w2f[kp][n] = (W2[2kp][n], W2[2kp+1][n])
        float a = W2[(2 * kp) * NH2 + n];
        float c = W2[(2 * kp + 1) * NH2 + n];
        uint32_t hi, lo; cvt_hilo2(make_float2(a, c), hi, lo);
        W2H[kp * W2STR + n] = hi;
        W2L[kp * W2STR + n] = lo;
    }
    if (tid < NH2) { sB2[tid] = b2[tid]; sW3v[tid] = W3[tid]; }
    // zero h1 tail rows 200..207 (read by last m-tile's GEMM2, results discarded)
    #pragma unroll
    for (int i = tid; i < 8 * HSTR; i += 256) {
        HH[200 * HSTR + i] = 0; HL[200 * HSTR + i] = 0;
    }
    __syncthreads();   // sQ visible

    // ---- Stage B: Weff = (W1b - W1c) + q .* W1d -> bf16 hi/lo, [h][e] ----
    #pragma unroll 4
    for (int i = tid; i < NE * NH1; i += 256) {
        int e = i >> 6, h = i & 63;
        float wb = W1[(NE + e) * NH1 + h];
        float wc = W1[(2 * NE + e) * NH1 + h];
        float wd = W1[(3 * NE + e) * NH1 + h];
        float w = wb - wc + sQ[e] * wd;
        __nv_bfloat16 hi = __float2bfloat16_rn(w);
        float lo = w - __bfloat162float(hi);
        *(unsigned short*)((char*)WHI + h * 272 + e * 2) = __bfloat16_as_ushort(hi);
        *(unsigned short*)((char*)WLO + h * 272 + e * 2) =
            __bfloat16_as_ushort(__float2bfloat16_rn(lo));
    }
    // qbias partials: qb[h] = b1[h] + sum_e q[e]*(W1a + W1c)[e][h]
    #pragma unroll
    for (int i = tid; i < 512; i += 256) {
        int h = i & 63, seg = i >> 6;
        float p = 0.f;
        int e0 = seg * 16;
        #pragma unroll 4
        for (int e = e0; e < e0 + 16; ++e)
            p += sQ[e] * (W1[e * NH1 + h] + W1[(2 * NE + e) * NH1 + h]);
        sQBp[seg * 64 + h] = p;
    }
    __syncthreads();
    if (tid < NH1) {
        float s = b1[tid];
        #pragma unroll
        for (int i = 0; i < 8; ++i) s += sQBp[i * 64 + tid];
        sQB[tid] = s;
    }
    __syncthreads();   // WHI/WLO, W2 fragments, HH/HL tail zeros, sQB all visible

    // ---- Fused GEMM1 + GEMM2 + scoring, per warp per m-tile ----
    {
        const int g = lane >> 2, kwid = lane & 3;
        const float* gK = keys + (size_t)b * NT * NE;
        const float b3v = b3[0];
        for (int m = wid; m < 13; m += 8) {
            int r0 = m * 16 + g;                  // <= 199 always
            int r1 = r0 + 8;
            int r1c = (r1 < NT) ? r1 : (NT - 1);  // clamp; results discarded
            const float* krow0 = gK + r0 * NE;
            const float* krow1 = gK + r1c * NE;

            // == GEMM1: h1 = K @ Weff, 3-term bf16, A direct from GMEM ==
            float acc[8][4];
            #pragma unroll
            for (int nt = 0; nt < 8; ++nt)
                #pragma unroll
                for (int j = 0; j < 4; ++j) acc[nt][j] = 0.f;

            #pragma unroll
            for (int ks = 0; ks < 8; ++ks) {
                int c0 = ks * 16 + kwid * 2;
                uint32_t ah[4], al[4];
                cvt_hilo2(*(const float2*)(krow0 + c0),     ah[0], al[0]);
                cvt_hilo2(*(const float2*)(krow1 + c0),     ah[1], al[1]);
                cvt_hilo2(*(const float2*)(krow0 + c0 + 8), ah[2], al[2]);
                cvt_hilo2(*(const float2*)(krow1 + c0 + 8), ah[3], al[3]);
                int kc = ks * 8 + kwid;
                #pragma unroll
                for (int nt = 0; nt < 8; ++nt) {
                    int rb = (nt * 8 + g) * KW + kc;
                    uint32_t bh[2], bl[2];
                    bh[0] = WHI[rb]; bh[1] = WHI[rb + 4];
                    bl[0] = WLO[rb]; bl[1] = WLO[rb + 4];
                    mma16816(acc[nt], ah, bh);
                    mma16816(acc[nt], al, bh);
                    mma16816(acc[nt], ah, bl);
                }
            }
            // == epilogue: relu(D + qbias) -> bf16 hi/lo pairs in HH/HL ==
            #pragma unroll
            for (int nt = 0; nt < 8; ++nt) {
                int h = nt * 8 + kwid * 2;
                float qa = sQB[h], qc = sQB[h + 1];
                int hp = nt * 4 + kwid;
                {
                    float2 v = make_float2(fmaxf(acc[nt][0] + qa, 0.f),
                                           fmaxf(acc[nt][1] + qc, 0.f));
                    uint32_t hi, lo; cvt_hilo2(v, hi, lo);
                    HH[r0 * HSTR + hp] = hi; HL[r0 * HSTR + hp] = lo;
                }
                if (r1 < NT) {
                    float2 v = make_float2(fmaxf(acc[nt][2] + qa, 0.f),
                                           fmaxf(acc[nt][3] + qc, 0.f));
                    uint32_t hi, lo; cvt_hilo2(v, hi, lo);
                    HH[r1 * HSTR + hp] = hi; HL[r1 * HSTR + hp] = lo;
                }
            }
            __syncwarp();   // h1 tile warp-visible

            // == GEMM2: h2 = h1 @ W2, 3-term bf16 ==
            float c2[4][4];
            #pragma unroll
            for (int nt = 0; nt < 4; ++nt)
                #pragma unroll
                for (int j = 0; j < 4; ++j) c2[nt][j] = 0.f;

            #pragma unroll
            for (int kt = 0; kt < 4; ++kt) {
                int a0 = r0 * HSTR + kt * 8 + kwid;
                int a1 = a0 + 8 * HSTR;
                uint32_t ah[4], al[4];
                ah[0] = HH[a0]; ah[1] = HH[a1]; ah[2] = HH[a0 + 4]; ah[3] = HH[a1 + 4];
                al[0] = HL[a0]; al[1] = HL[a1]; al[2] = HL[a0 + 4]; al[3] = HL[a1 + 4];
                #pragma unroll
                for (int nt = 0; nt < 4; ++nt) {
                    int bb = (kt * 8 + kwid) * W2STR + nt * 8 + g;
                    uint32_t bh[2], bl[2];
                    bh[0] = W2H[bb]; bh[1] = W2H[bb + 4 * W2STR];
                    bl[0] = W2L[bb]; bl[1] = W2L[bb + 4 * W2STR];
                    mma16816(c2[nt], ah, bh);
                    mma16816(c2[nt], al, bh);
                    mma16816(c2[nt], ah, bl);
                }
            }
            // == score epilogue: sum relu(h2 + b2) * W3 over 32 cols ==
            float p0 = 0.f, p1 = 0.f;
            #pragma unroll
            for (int nt = 0; nt < 4; ++nt) {
                int h0 = nt * 8 + kwid * 2;
                float b2a = sB2[h0], b2b = sB2[h0 + 1];
                float w3a = sW3v[h0], w3b = sW3v[h0 + 1];
                p0 += fmaxf(c2[nt][0] + b2a, 0.f) * w3a
                    + fmaxf(c2[nt][1] + b2b, 0.f) * w3b;
                p1 += fmaxf(c2[nt][2] + b2a, 0.f) * w3a
                    + fmaxf(c2[nt][3] + b2b, 0.f) * w3b;
            }
            p0 += __shfl_xor_sync(0xffffffffu, p0, 1);
            p0 += __shfl_xor_sync(0xffffffffu, p0, 2);
            p1 += __shfl_xor_sync(0xffffffffu, p1, 1);
            p1 += __shfl_xor_sync(0xffffffffu, p1, 2);
            if (kwid == 0) {
                sS[r0] = (keys_id[b * NT + r0] != 0) ? (p0 + b3v) : NEG_INF;
                if (r1 < NT)
                    sS[r1] = (keys_id[b * NT + r1] != 0) ? (p1 + b3v) : NEG_INF;
            }
        }
    }
    __syncthreads();

    // ---- masked softmax over T ----
    {
        float v = (tid < NT) ? sS[tid] : -3.0e38f;
        float m = v;
        #pragma unroll
        for (int o = 16; o; o >>= 1) m = fmaxf(m, __shfl_xor_sync(0xffffffffu, m, o));
        if (lane == 0) sRed[wid] = m;
        __syncthreads();
        float mx = sRed[0];
        #pragma unroll
        for (int i = 1; i < 8; ++i) mx = fmaxf(mx, sRed[i]);
        float p = (tid < NT) ? __expf(v - mx) : 0.f;
        float s = p;
        #pragma unroll
        for (int o = 16; o; o >>= 1) s += __shfl_xor_sync(0xffffffffu, s, o);
        __syncthreads();
        if (lane == 0) sRed[wid] = s;
        __syncthreads();
        float tot = 0.f;
        #pragma unroll
        for (int i = 0; i < 8; ++i) tot += sRed[i];
        if (tid < NT) sS[tid] = p / tot;
    }
    __syncthreads();

    // ---- pooling: out[e] = (1/T) * sum_t w[t] * K[t][e]  (keys from L2, fp32) ----
    {
        int pr = tid & 63;      // e-pair index
        int seg = tid >> 6;     // 4 t-segments of 50
        const ull* gK2 = (const ull*)(keys + (size_t)b * NT * NE);
        float ax = 0.f, ay = 0.f;
        int t0 = seg * 50;
        #pragma unroll 5
        for (int t = t0; t < t0 + 50; ++t) {
            float wv = sS[t];
            float2 kv = unpack2(gK2[t * 64 + pr]);
            ax = fmaf(wv, kv.x, ax);
            ay = fmaf(wv, kv.y, ay);
        }
        sPool[seg * 128 + 2 * pr]     = ax;
        sPool[seg * 128 + 2 * pr + 1] = ay;
    }
    __syncthreads();
    if (tid < NE) {
        float r = sPool[tid] + sPool[128 + tid] + sPool[256 + tid] + sPool[384 + tid];
        out[b * NE + tid] = r * (1.0f / NT);
    }
}

extern "C" void kernel_launch(void* const* d_in, const int* in_sizes, int n_in,
                              void* d_out, int out_size) {
    const float* queries = (const float*)d_in[0];
    const float* keys    = (const float*)d_in[1];
    const int*   keys_id = (const int*)  d_in[2];
    const float* W1      = (const float*)d_in[3];
    const float* b1      = (const float*)d_in[4];
    const float* W2      = (const float*)d_in[5];
    const float* b2      = (const float*)d_in[6];
    const float* W3      = (const float*)d_in[7];
    const float* b3      = (const float*)d_in[8];
    float* out = (float*)d_out;

    cudaFuncSetAttribute(attn_kernel,
                         cudaFuncAttributeMaxDynamicSharedMemorySize, SMEM_TOTAL);
    attn_kernel<<<NB, 256, SMEM_TOTAL>>>(queries, keys, keys_id,
                                         W1, b1, W2, b2, W3, b3, out);
}

// round 16
// speedup vs baseline: 3.0067x; 1.0430x over previous
#include <cuda_runtime.h>
#include <cuda_bf16.h>
#include <cstdint>

typedef unsigned long long ull;

#define NB 2048
#define NT 200
#define NE 128
#define NH1 64
#define NH2 32
#define NEG_INF (-4294967295.0f)

// Weff tile row stride in words (64 e-pair words + 4 pad)
#define KW 68
// W2 frag tile row stride in words (32 n + 8 pad)
#define W2STR 40

// ---- SMEM layout (bytes), total 51136 ----
#define OFF_WHI  0        // 64 x 68 x 4 = 17408
#define OFF_WLO  17408    // 17408
#define OFF_W2H  34816    // 32 x 40 x 4 = 5120
#define OFF_W2L  39936    // 5120
#define OFF_SQ   45056    // 512
#define OFF_SQBP 45568    // 2048
#define OFF_SQB  47616    // 256
#define OFF_SS   47872    // 832
#define OFF_SB2  48704    // 128
#define OFF_SW3  48832    // 128
#define OFF_SRED 48960    // 128
#define OFF_SPOOL 49088   // 2048
#define SMEM_TOTAL 51136

__device__ __forceinline__ float2 unpack2(ull v) {
    float2 r;
    asm("mov.b64 {%0, %1}, %2;" : "=f"(r.x), "=f"(r.y) : "l"(v));
    return r;
}
__device__ __forceinline__ void mma16816(float* c, const uint32_t* a, const uint32_t* b) {
    asm volatile("mma.sync.aligned.m16n8k16.row.col.f32.bf16.bf16.f32 "
        "{%0,%1,%2,%3}, {%4,%5,%6,%7}, {%8,%9}, {%0,%1,%2,%3};"
        : "+f"(c[0]), "+f"(c[1]), "+f"(c[2]), "+f"(c[3])
        : "r"(a[0]), "r"(a[1]), "r"(a[2]), "r"(a[3]), "r"(b[0]), "r"(b[1]));
}
// (v.x, v.y) -> packed bf16x2 hi (x in low half) and packed bf16x2 residual lo
__device__ __forceinline__ void cvt_hilo2(float2 v, uint32_t& hi, uint32_t& lo) {
    uint32_t h;
    asm("cvt.rn.bf16x2.f32 %0, %1, %2;" : "=r"(h) : "f"(v.y), "f"(v.x));
    float hx = __uint_as_float(h << 16);
    float hy = __uint_as_float(h & 0xffff0000u);
    float lx = v.x - hx, ly = v.y - hy;
    uint32_t l;
    asm("cvt.rn.bf16x2.f32 %0, %1, %2;" : "=r"(l) : "f"(ly), "f"(lx));
    hi = h; lo = l;
}

// GEMM2 + score for one m-tile, consuming GEMM1 accumulators in registers.
// acc[nt][j] holds h1 rows (r0, r0+8) cols nt*8 + 2*kwid (+1).
__device__ __forceinline__ void tail_score(
    const float acc[8][4], int r0, int r1,
    const uint32_t* __restrict__ W2H, const uint32_t* __restrict__ W2L,
    const float* __restrict__ sQB, const float* __restrict__ sB2,
    const float* __restrict__ sW3v, float b3v,
    const int* __restrict__ kid, float* __restrict__ sS,
    int g, int kwid)
{
    // re-pack accumulators -> GEMM2 A-fragments (relu + qbias, bf16 hi/lo)
    uint32_t AH[16], AL[16];
    #pragma unroll
    for (int kt = 0; kt < 4; ++kt) {
        int nt0 = 2 * kt, nt1 = 2 * kt + 1;
        float qa0 = sQB[nt0 * 8 + 2 * kwid], qb0 = sQB[nt0 * 8 + 2 * kwid + 1];
        float qa1 = sQB[nt1 * 8 + 2 * kwid], qb1 = sQB[nt1 * 8 + 2 * kwid + 1];
        cvt_hilo2(make_float2(fmaxf(acc[nt0][0] + qa0, 0.f),
                              fmaxf(acc[nt0][1] + qb0, 0.f)), AH[kt*4+0], AL[kt*4+0]);
        cvt_hilo2(make_float2(fmaxf(acc[nt0][2] + qa0, 0.f),
                              fmaxf(acc[nt0][3] + qb0, 0.f)), AH[kt*4+1], AL[kt*4+1]);
        cvt_hilo2(make_float2(fmaxf(acc[nt1][0] + qa1, 0.f),
                              fmaxf(acc[nt1][1] + qb1, 0.f)), AH[kt*4+2], AL[kt*4+2]);
        cvt_hilo2(make_float2(fmaxf(acc[nt1][2] + qa1, 0.f),
                              fmaxf(acc[nt1][3] + qb1, 0.f)), AH[kt*4+3], AL[kt*4+3]);
    }
    // GEMM2: h2 = h1 @ W2, 3-term bf16
    float c2[4][4];
    #pragma unroll
    for (int nt = 0; nt < 4; ++nt)
        #pragma unroll
        for (int j = 0; j < 4; ++j) c2[nt][j] = 0.f;
    #pragma unroll
    for (int kt = 0; kt < 4; ++kt) {
        #pragma unroll
        for (int nt = 0; nt < 4; ++nt) {
            int bb = (kt * 8 + kwid) * W2STR + nt * 8 + g;
            uint32_t bh[2], bl[2];
            bh[0] = W2H[bb]; bh[1] = W2H[bb + 4 * W2STR];
            bl[0] = W2L[bb]; bl[1] = W2L[bb + 4 * W2STR];
            mma16816(c2[nt], &AH[kt*4], bh);
            mma16816(c2[nt], &AL[kt*4], bh);
            mma16816(c2[nt], &AH[kt*4], bl);
        }
    }
    // score: sum relu(h2 + b2) * W3 over 32 cols
    float p0 = 0.f, p1 = 0.f;
    #pragma unroll
    for (int nt = 0; nt < 4; ++nt) {
        int h0 = nt * 8 + kwid * 2;
        float b2a = sB2[h0], b2b = sB2[h0 + 1];
        float w3a = sW3v[h0], w3b = sW3v[h0 + 1];
        p0 += fmaxf(c2[nt][0] + b2a, 0.f) * w3a + fmaxf(c2[nt][1] + b2b, 0.f) * w3b;
        p1 += fmaxf(c2[nt][2] + b2a, 0.f) * w3a + fmaxf(c2[nt][3] + b2b, 0.f) * w3b;
    }
    p0 += __shfl_xor_sync(0xffffffffu, p0, 1);
    p0 += __shfl_xor_sync(0xffffffffu, p0, 2);
    p1 += __shfl_xor_sync(0xffffffffu, p1, 1);
    p1 += __shfl_xor_sync(0xffffffffu, p1, 2);
    if (kwid == 0) {
        sS[r0] = (kid[r0] != 0) ? (p0 + b3v) : NEG_INF;
        if (r1 < NT)
            sS[r1] = (kid[r1] != 0) ? (p1 + b3v) : NEG_INF;
    }
}

__global__ __launch_bounds__(256, 2)
void attn_kernel(const float* __restrict__ queries, const float* __restrict__ keys,
                 const int* __restrict__ keys_id, const float* __restrict__ W1,
                 const float* __restrict__ b1, const float* __restrict__ W2,
                 const float* __restrict__ b2, const float* __restrict__ W3,
                 const float* __restrict__ b3, float* __restrict__ out)
{
    extern __shared__ char smem[];
    const int tid = threadIdx.x;
    const int wid = tid >> 5;
    const int lane = tid & 31;
    const int b = blockIdx.x;

    uint32_t* WHI = (uint32_t*)(smem + OFF_WHI);
    uint32_t* WLO = (uint32_t*)(smem + OFF_WLO);
    uint32_t* W2H = (uint32_t*)(smem + OFF_W2H);
    uint32_t* W2L = (uint32_t*)(smem + OFF_W2L);
    float* sQ    = (float*)(smem + OFF_SQ);
    float* sQBp  = (float*)(smem + OFF_SQBP);
    float* sQB   = (float*)(smem + OFF_SQB);
    float* sS    = (float*)(smem + OFF_SS);
    float* sB2   = (float*)(smem + OFF_SB2);
    float* sW3v  = (float*)(smem + OFF_SW3);
    float* sRed  = (float*)(smem + OFF_SRED);
    float* sPool = (float*)(smem + OFF_SPOOL);

    // ---- Stage A: small loads; W2 frag pack (bf16 hi/lo) ----
    if (tid < NE) sQ[tid] = queries[b * NE + tid];
    #pragma unroll
    for (int i = tid; i < 1024; i += 256) {
        int kp = i >> 5, n = i & 31;    // (W2[2kp][n], W2[2kp+1][n])
        float a = W2[(2 * kp) * NH2 + n];
        float c = W2[(2 * kp + 1) * NH2 + n];
        uint32_t hi, lo; cvt_hilo2(make_float2(a, c), hi, lo);
        W2H[kp * W2STR + n] = hi;
        W2L[kp * W2STR + n] = lo;
    }
    if (tid < NH2) { sB2[tid] = b2[tid]; sW3v[tid] = W3[tid]; }
    __syncthreads();   // sQ visible

    // ---- Stage B: Weff = (W1b - W1c) + q .* W1d -> bf16 hi/lo, [h][e] ----
    #pragma unroll 4
    for (int i = tid; i < NE * NH1; i += 256) {
        int e = i >> 6, h = i & 63;
        float wb = W1[(NE + e) * NH1 + h];
        float wc = W1[(2 * NE + e) * NH1 + h];
        float wd = W1[(3 * NE + e) * NH1 + h];
        float w = wb - wc + sQ[e] * wd;
        __nv_bfloat16 hi = __float2bfloat16_rn(w);
        float lo = w - __bfloat162float(hi);
        *(unsigned short*)((char*)WHI + h * 272 + e * 2) = __bfloat16_as_ushort(hi);
        *(unsigned short*)((char*)WLO + h * 272 + e * 2) =
            __bfloat16_as_ushort(__float2bfloat16_rn(lo));
    }
    // qbias partials: qb[h] = b1[h] + sum_e q[e]*(W1a + W1c)[e][h]
    #pragma unroll
    for (int i = tid; i < 512; i += 256) {
        int h = i & 63, seg = i >> 6;
        float p = 0.f;
        int e0 = seg * 16;
        #pragma unroll 4
        for (int e = e0; e < e0 + 16; ++e)
            p += sQ[e] * (W1[e * NH1 + h] + W1[(2 * NE + e) * NH1 + h]);
        sQBp[seg * 64 + h] = p;
    }
    __syncthreads();
    if (tid < NH1) {
        float s = b1[tid];
        #pragma unroll
        for (int i = 0; i < 8; ++i) s += sQBp[i * 64 + tid];
        sQB[tid] = s;
    }
    __syncthreads();   // WHI/WLO, W2 frags, sQB visible

    // ---- Fused GEMM1 (dual m-tile, shared W frags) + GEMM2 + scoring ----
    {
        const int g = lane >> 5 ? 0 : (lane >> 2);   // g = lane>>2
        const int kwid = lane & 3;
        const int gg = lane >> 2;
        const float* gK = keys + (size_t)b * NT * NE;
        const int* kid = keys_id + b * NT;
        const float b3v = b3[0];

        const int m1 = wid;            // tile 1: rows m1*16 + {gg, gg+8}, always < 200
        const int m2 = wid + 8;        // tile 2 (warps 0-4 only)
        const bool has2 = (m2 < 13);

        int r1a = m1 * 16 + gg, r1b = r1a + 8;
        int r2a = has2 ? (m2 * 16 + gg) : r1a;
        int r2b_real = r2a + 8;
        int r2b = (r2b_real < NT) ? r2b_real : (NT - 1);   // clamp; discarded

        const float* k1a = gK + r1a * NE;
        const float* k1b = gK + r1b * NE;
        const float* k2a = gK + r2a * NE;
        const float* k2b = gK + r2b * NE;

        float acc1[8][4], acc2[8][4];
        #pragma unroll
        for (int nt = 0; nt < 8; ++nt)
            #pragma unroll
            for (int j = 0; j < 4; ++j) { acc1[nt][j] = 0.f; acc2[nt][j] = 0.f; }

        #pragma unroll
        for (int ks = 0; ks < 8; ++ks) {
            int c0 = ks * 16 + kwid * 2;
            uint32_t ah1[4], al1[4], ah2[4], al2[4];
            cvt_hilo2(*(const float2*)(k1a + c0),     ah1[0], al1[0]);
            cvt_hilo2(*(const float2*)(k1b + c0),     ah1[1], al1[1]);
            cvt_hilo2(*(const float2*)(k1a + c0 + 8), ah1[2], al1[2]);
            cvt_hilo2(*(const float2*)(k1b + c0 + 8), ah1[3], al1[3]);
            if (has2) {
                cvt_hilo2(*(const float2*)(k2a + c0),     ah2[0], al2[0]);
                cvt_hilo2(*(const float2*)(k2b + c0),     ah2[1], al2[1]);
                cvt_hilo2(*(const float2*)(k2a + c0 + 8), ah2[2], al2[2]);
                cvt_hilo2(*(const float2*)(k2b + c0 + 8), ah2[3], al2[3]);
            }
            int kc = ks * 8 + kwid;
            #pragma unroll
            for (int nt = 0; nt < 8; ++nt) {
                int rb = (nt * 8 + gg) * KW + kc;
                uint32_t bh[2], bl[2];
                bh[0] = WHI[rb]; bh[1] = WHI[rb + 4];
                bl[0] = WLO[rb]; bl[1] = WLO[rb + 4];
                mma16816(acc1[nt], ah1, bh);
                mma16816(acc1[nt], al1, bh);
                mma16816(acc1[nt], ah1, bl);
                if (has2) {
                    mma16816(acc2[nt], ah2, bh);
                    mma16816(acc2[nt], al2, bh);
                    mma16816(acc2[nt], ah2, bl);
                }
            }
        }
        tail_score(acc1, r1a, r1b, W2H, W2L, sQB, sB2, sW3v, b3v, kid, sS, gg, kwid);
        if (has2)
            tail_score(acc2, r2a, r2b_real, W2H, W2L, sQB, sB2, sW3v, b3v, kid, sS, gg, kwid);
    }
    __syncthreads();

    // ---- masked softmax over T ----
    {
        float v = (tid < NT) ? sS[tid] : -3.0e38f;
        float m = v;
        #pragma unroll
        for (int o = 16; o; o >>= 1) m = fmaxf(m, __shfl_xor_sync(0xffffffffu, m, o));
        if (lane == 0) sRed[wid] = m;
        __syncthreads();
        float mx = sRed[0];
        #pragma unroll
        for (int i = 1; i < 8; ++i) mx = fmaxf(mx, sRed[i]);
        float p = (tid < NT) ? __expf(v - mx) : 0.f;
        float s = p;
        #pragma unroll
        for (int o = 16; o; o >>= 1) s += __shfl_xor_sync(0xffffffffu, s, o);
        __syncthreads();
        if (lane == 0) sRed[wid] = s;
        __syncthreads();
        float tot = 0.f;
        #pragma unroll
        for (int i = 0; i < 8; ++i) tot += sRed[i];
        if (tid < NT) sS[tid] = p / tot;
    }
    __syncthreads();

    // ---- pooling: out[e] = (1/T) * sum_t w[t] * K[t][e]  (keys from L2, fp32) ----
    {
        int pr = tid & 63;
        int seg = tid >> 6;
        const ull* gK2 = (const ull*)(keys + (size_t)b * NT * NE);
        float ax = 0.f, ay = 0.f;
        int t0 = seg * 50;
        #pragma unroll 5
        for (int t = t0; t < t0 + 50; ++t) {
            float wv = sS[t];
            float2 kv = unpack2(gK2[t * 64 + pr]);
            ax = fmaf(wv, kv.x, ax);
            ay = fmaf(wv, kv.y, ay);
        }
        sPool[seg * 128 + 2 * pr]     = ax;
        sPool[seg * 128 + 2 * pr + 1] = ay;
    }
    __syncthreads();
    if (tid < NE) {
        float r = sPool[tid] + sPool[128 + tid] + sPool[256 + tid] + sPool[384 + tid];
        out[b * NE + tid] = r * (1.0f / NT);
    }
}

extern "C" void kernel_launch(void* const* d_in, const int* in_sizes, int n_in,
                              void* d_out, int out_size) {
    const float* queries = (const float*)d_in[0];
    const float* keys    = (const float*)d_in[1];
    const int*   keys_id = (const int*)  d_in[2];
    const float* W1      = (const float*)d_in[3];
    const float* b1      = (const float*)d_in[4];
    const float* W2      = (const float*)d_in[5];
    const float* b2      = (const float*)d_in[6];
    const float* W3      = (const float*)d_in[7];
    const float* b3      = (const float*)d_in[8];
    float* out = (float*)d_out;

    cudaFuncSetAttribute(attn_kernel,
                         cudaFuncAttributeMaxDynamicSharedMemorySize, SMEM_TOTAL);
    attn_kernel<<<NB, 256, SMEM_TOTAL>>>(queries, keys, keys_id,
                                         W1, b1, W2, b2, W3, b3, out);
}

// round 17
// speedup vs baseline: 3.1910x; 1.0613x over previous
#include <cuda_runtime.h>
#include <cuda_bf16.h>
#include <cstdint>

typedef unsigned long long ull;

#define NB 2048
#define NT 200
#define NE 128
#define NH1 64
#define NH2 32
#define NEG_INF (-4294967295.0f)

// Weff tile row stride in words (64 e-pair words interleaved + 8 pad)
// 72 mod 32 = 8 -> LDS.64 banks 8g+2kwid, conflict-free per 16-lane phase
#define KW 72
// W2 frag tile row stride in words (32 n + 8 pad)
#define W2STR 40

// ---- SMEM layout (bytes), total 53184 -> 3 CTAs/SM ----
#define OFF_WHI  0        // 64 x 72 x 4 = 18432
#define OFF_WLO  18432    // 18432
#define OFF_W2H  36864    // 32 x 40 x 4 = 5120
#define OFF_W2L  41984    // 5120
#define OFF_SQ   47104    // 512
#define OFF_SQBP 47616    // 2048
#define OFF_SQB  49664    // 256
#define OFF_SS   49920    // 832
#define OFF_SB2  50752    // 128
#define OFF_SW3  50880    // 128
#define OFF_SRED 51008    // 128
#define OFF_SPOOL 51136   // 2048
#define SMEM_TOTAL 53184

__device__ __forceinline__ float2 unpack2(ull v) {
    float2 r;
    asm("mov.b64 {%0, %1}, %2;" : "=f"(r.x), "=f"(r.y) : "l"(v));
    return r;
}
__device__ __forceinline__ void mma16816(float* c, const uint32_t* a, const uint32_t* b) {
    asm volatile("mma.sync.aligned.m16n8k16.row.col.f32.bf16.bf16.f32 "
        "{%0,%1,%2,%3}, {%4,%5,%6,%7}, {%8,%9}, {%0,%1,%2,%3};"
        : "+f"(c[0]), "+f"(c[1]), "+f"(c[2]), "+f"(c[3])
        : "r"(a[0]), "r"(a[1]), "r"(a[2]), "r"(a[3]), "r"(b[0]), "r"(b[1]));
}
// (v.x, v.y) -> packed bf16x2 hi (x in low half) and packed bf16x2 residual lo
__device__ __forceinline__ void cvt_hilo2(float2 v, uint32_t& hi, uint32_t& lo) {
    uint32_t h;
    asm("cvt.rn.bf16x2.f32 %0, %1, %2;" : "=r"(h) : "f"(v.y), "f"(v.x));
    float hx = __uint_as_float(h << 16);
    float hy = __uint_as_float(h & 0xffff0000u);
    float lx = v.x - hx, ly = v.y - hy;
    uint32_t l;
    asm("cvt.rn.bf16x2.f32 %0, %1, %2;" : "=r"(l) : "f"(ly), "f"(lx));
    hi = h; lo = l;
}

// GEMM2 + score for one m-tile, consuming GEMM1 accumulators in registers.
// acc[nt][j] holds h1 rows (r0, r0+8) cols nt*8 + 2*kwid (+1).
__device__ __forceinline__ void tail_score(
    const float acc[8][4], int r0, int r1,
    const uint32_t* __restrict__ W2H, const uint32_t* __restrict__ W2L,
    const float* __restrict__ sQB, const float* __restrict__ sB2,
    const float* __restrict__ sW3v, float b3v,
    const int* __restrict__ kid, float* __restrict__ sS,
    int g, int kwid)
{
    // re-pack accumulators -> GEMM2 A-fragments (relu + qbias, bf16 hi/lo)
    uint32_t AH[16], AL[16];
    #pragma unroll
    for (int kt = 0; kt < 4; ++kt) {
        int nt0 = 2 * kt, nt1 = 2 * kt + 1;
        float qa0 = sQB[nt0 * 8 + 2 * kwid], qb0 = sQB[nt0 * 8 + 2 * kwid + 1];
        float qa1 = sQB[nt1 * 8 + 2 * kwid], qb1 = sQB[nt1 * 8 + 2 * kwid + 1];
        cvt_hilo2(make_float2(fmaxf(acc[nt0][0] + qa0, 0.f),
                              fmaxf(acc[nt0][1] + qb0, 0.f)), AH[kt*4+0], AL[kt*4+0]);
        cvt_hilo2(make_float2(fmaxf(acc[nt0][2] + qa0, 0.f),
                              fmaxf(acc[nt0][3] + qb0, 0.f)), AH[kt*4+1], AL[kt*4+1]);
        cvt_hilo2(make_float2(fmaxf(acc[nt1][0] + qa1, 0.f),
                              fmaxf(acc[nt1][1] + qb1, 0.f)), AH[kt*4+2], AL[kt*4+2]);
        cvt_hilo2(make_float2(fmaxf(acc[nt1][2] + qa1, 0.f),
                              fmaxf(acc[nt1][3] + qb1, 0.f)), AH[kt*4+3], AL[kt*4+3]);
    }
    // GEMM2: h2 = h1 @ W2, 3-term bf16
    float c2[4][4];
    #pragma unroll
    for (int nt = 0; nt < 4; ++nt)
        #pragma unroll
        for (int j = 0; j < 4; ++j) c2[nt][j] = 0.f;
    #pragma unroll
    for (int kt = 0; kt < 4; ++kt) {
        #pragma unroll
        for (int nt = 0; nt < 4; ++nt) {
            int bb = (kt * 8 + kwid) * W2STR + nt * 8 + g;
            uint32_t bh[2], bl[2];
            bh[0] = W2H[bb]; bh[1] = W2H[bb + 4 * W2STR];
            bl[0] = W2L[bb]; bl[1] = W2L[bb + 4 * W2STR];
            mma16816(c2[nt], &AH[kt*4], bh);
            mma16816(c2[nt], &AL[kt*4], bh);
            mma16816(c2[nt], &AH[kt*4], bl);
        }
    }
    // score: sum relu(h2 + b2) * W3 over 32 cols
    float p0 = 0.f, p1 = 0.f;
    #pragma unroll
    for (int nt = 0; nt < 4; ++nt) {
        int h0 = nt * 8 + kwid * 2;
        float b2a = sB2[h0], b2b = sB2[h0 + 1];
        float w3a = sW3v[h0], w3b = sW3v[h0 + 1];
        p0 += fmaxf(c2[nt][0] + b2a, 0.f) * w3a + fmaxf(c2[nt][1] + b2b, 0.f) * w3b;
        p1 += fmaxf(c2[nt][2] + b2a, 0.f) * w3a + fmaxf(c2[nt][3] + b2b, 0.f) * w3b;
    }
    p0 += __shfl_xor_sync(0xffffffffu, p0, 1);
    p0 += __shfl_xor_sync(0xffffffffu, p0, 2);
    p1 += __shfl_xor_sync(0xffffffffu, p1, 1);
    p1 += __shfl_xor_sync(0xffffffffu, p1, 2);
    if (kwid == 0) {
        sS[r0] = (kid[r0] != 0) ? (p0 + b3v) : NEG_INF;
        if (r1 < NT)
            sS[r1] = (kid[r1] != 0) ? (p1 + b3v) : NEG_INF;
    }
}

__global__ __launch_bounds__(256, 3)
void attn_kernel(const float* __restrict__ queries, const float* __restrict__ keys,
                 const int* __restrict__ keys_id, const float* __restrict__ W1,
                 const float* __restrict__ b1, const float* __restrict__ W2,
                 const float* __restrict__ b2, const float* __restrict__ W3,
                 const float* __restrict__ b3, float* __restrict__ out)
{
    extern __shared__ char smem[];
    const int tid = threadIdx.x;
    const int wid = tid >> 5;
    const int lane = tid & 31;
    const int b = blockIdx.x;

    uint32_t* WHI = (uint32_t*)(smem + OFF_WHI);
    uint32_t* WLO = (uint32_t*)(smem + OFF_WLO);
    uint32_t* W2H = (uint32_t*)(smem + OFF_W2H);
    uint32_t* W2L = (uint32_t*)(smem + OFF_W2L);
    float* sQ    = (float*)(smem + OFF_SQ);
    float* sQBp  = (float*)(smem + OFF_SQBP);
    float* sQB   = (float*)(smem + OFF_SQB);
    float* sS    = (float*)(smem + OFF_SS);
    float* sB2   = (float*)(smem + OFF_SB2);
    float* sW3v  = (float*)(smem + OFF_SW3);
    float* sRed  = (float*)(smem + OFF_SRED);
    float* sPool = (float*)(smem + OFF_SPOOL);

    // ---- Stage A: small loads; W2 frag pack (bf16 hi/lo) ----
    if (tid < NE) sQ[tid] = queries[b * NE + tid];
    #pragma unroll
    for (int i = tid; i < 1024; i += 256) {
        int kp = i >> 5, n = i & 31;    // (W2[2kp][n], W2[2kp+1][n])
        float a = W2[(2 * kp) * NH2 + n];
        float c = W2[(2 * kp + 1) * NH2 + n];
        uint32_t hi, lo; cvt_hilo2(make_float2(a, c), hi, lo);
        W2H[kp * W2STR + n] = hi;
        W2L[kp * W2STR + n] = lo;
    }
    if (tid < NH2) { sB2[tid] = b2[tid]; sW3v[tid] = W3[tid]; }
    __syncthreads();   // sQ visible

    // ---- Stage B: Weff = (W1b - W1c) + q .* W1d -> bf16 hi/lo ----
    // Interleaved word layout: within each ks-group of 8 e-pair words,
    // word pairs (j, j+4) stored adjacently -> GEMM1 loads via one LDS.64.
    #pragma unroll 4
    for (int i = tid; i < NE * NH1; i += 256) {
        int e = i >> 6, h = i & 63;
        float wb = W1[(NE + e) * NH1 + h];
        float wc = W1[(2 * NE + e) * NH1 + h];
        float wd = W1[(3 * NE + e) * NH1 + h];
        float w = wb - wc + sQ[e] * wd;
        __nv_bfloat16 hi = __float2bfloat16_rn(w);
        float lo = w - __bfloat162float(hi);
        int p = e >> 1, ks = p >> 3, j = p & 7;
        int word = ks * 8 + ((j & 4) ? ((j & 3) * 2 + 1) : (j * 2));
        int byt = h * (KW * 4) + word * 4 + (e & 1) * 2;
        *(unsigned short*)((char*)WHI + byt) = __bfloat16_as_ushort(hi);
        *(unsigned short*)((char*)WLO + byt) =
            __bfloat16_as_ushort(__float2bfloat16_rn(lo));
    }
    // qbias partials: qb[h] = b1[h] + sum_e q[e]*(W1a + W1c)[e][h]
    #pragma unroll
    for (int i = tid; i < 512; i += 256) {
        int h = i & 63, seg = i >> 6;
        float p = 0.f;
        int e0 = seg * 16;
        #pragma unroll 4
        for (int e = e0; e < e0 + 16; ++e)
            p += sQ[e] * (W1[e * NH1 + h] + W1[(2 * NE + e) * NH1 + h]);
        sQBp[seg * 64 + h] = p;
    }
    __syncthreads();
    if (tid < NH1) {
        float s = b1[tid];
        #pragma unroll
        for (int i = 0; i < 8; ++i) s += sQBp[i * 64 + tid];
        sQB[tid] = s;
    }
    __syncthreads();   // WHI/WLO, W2 frags, sQB visible

    // ---- Fused GEMM1 + GEMM2 + scoring; one m-tile per warp iteration ----
    {
        const int gg = lane >> 2;
        const int kwid = lane & 3;
        const float* gK = keys + (size_t)b * NT * NE;
        const int* kid = keys_id + b * NT;
        const float b3v = b3[0];

        for (int m = wid; m < 13; m += 8) {
            int r0 = m * 16 + gg;                 // <= 199 always
            int r1 = r0 + 8;
            int r1c = (r1 < NT) ? r1 : (NT - 1);  // clamp; results discarded
            const float* ka = gK + r0 * NE;
            const float* kb = gK + r1c * NE;

            float acc[8][4];
            #pragma unroll
            for (int nt = 0; nt < 8; ++nt)
                #pragma unroll
                for (int j = 0; j < 4; ++j) acc[nt][j] = 0.f;

            #pragma unroll
            for (int ks = 0; ks < 8; ++ks) {
                int c0 = ks * 16 + kwid * 2;
                uint32_t ah[4], al[4];
                cvt_hilo2(*(const float2*)(ka + c0),     ah[0], al[0]);
                cvt_hilo2(*(const float2*)(kb + c0),     ah[1], al[1]);
                cvt_hilo2(*(const float2*)(ka + c0 + 8), ah[2], al[2]);
                cvt_hilo2(*(const float2*)(kb + c0 + 8), ah[3], al[3]);
                int wb0 = ks * 8 + kwid * 2;
                #pragma unroll
                for (int nt = 0; nt < 8; ++nt) {
                    int row = (nt * 8 + gg) * KW + wb0;
                    uint2 bh = *(const uint2*)(WHI + row);   // LDS.64
                    uint2 bl = *(const uint2*)(WLO + row);
                    uint32_t bhr[2] = { bh.x, bh.y };
                    uint32_t blr[2] = { bl.x, bl.y };
                    mma16816(acc[nt], ah, bhr);
                    mma16816(acc[nt], al, bhr);
                    mma16816(acc[nt], ah, blr);
                }
            }
            tail_score(acc, r0, r1, W2H, W2L, sQB, sB2, sW3v, b3v, kid, sS, gg, kwid);
        }
    }
    __syncthreads();

    // ---- masked softmax over T ----
    {
        float v = (tid < NT) ? sS[tid] : -3.0e38f;
        float m = v;
        #pragma unroll
        for (int o = 16; o; o >>= 1) m = fmaxf(m, __shfl_xor_sync(0xffffffffu, m, o));
        if (lane == 0) sRed[wid] = m;
        __syncthreads();
        float mx = sRed[0];
        #pragma unroll
        for (int i = 1; i < 8; ++i) mx = fmaxf(mx, sRed[i]);
        float p = (tid < NT) ? __expf(v - mx) : 0.f;
        float s = p;
        #pragma unroll
        for (int o = 16; o; o >>= 1) s += __shfl_xor_sync(0xffffffffu, s, o);
        __syncthreads();
        if (lane == 0) sRed[wid] = s;
        __syncthreads();
        float tot = 0.f;
        #pragma unroll
        for (int i = 0; i < 8; ++i) tot += sRed[i];
        if (tid < NT) sS[tid] = p / tot;
    }
    __syncthreads();

    // ---- pooling: out[e] = (1/T) * sum_t w[t] * K[t][e]  (keys from L2, fp32) ----
    {
        int pr = tid & 63;
        int seg = tid >> 6;
        const ull* gK2 = (const ull*)(keys + (size_t)b * NT * NE);
        float ax = 0.f, ay = 0.f;
        int t0 = seg * 50;
        #pragma unroll 5
        for (int t = t0; t < t0 + 50; ++t) {
            float wv = sS[t];
            float2 kv = unpack2(gK2[t * 64 + pr]);
            ax = fmaf(wv, kv.x, ax);
            ay = fmaf(wv, kv.y, ay);
        }
        sPool[seg * 128 + 2 * pr]     = ax;
        sPool[seg * 128 + 2 * pr + 1] = ay;
    }
    __syncthreads();
    if (tid < NE) {
        float r = sPool[tid] + sPool[128 + tid] + sPool[256 + tid] + sPool[384 + tid];
        out[b * NE + tid] = r * (1.0f / NT);
    }
}

extern "C" void kernel_launch(void* const* d_in, const int* in_sizes, int n_in,
                              void* d_out, int out_size) {
    const float* queries = (const float*)d_in[0];
    const float* keys    = (const float*)d_in[1];
    const int*   keys_id = (const int*)  d_in[2];
    const float* W1      = (const float*)d_in[3];
    const float* b1      = (const float*)d_in[4];
    const float* W2      = (const float*)d_in[5];
    const float* b2      = (const float*)d_in[6];
    const float* W3      = (const float*)d_in[7];
    const float* b3      = (const float*)d_in[8];
    float* out = (float*)d_out;

    cudaFuncSetAttribute(attn_kernel,
                         cudaFuncAttributeMaxDynamicSharedMemorySize, SMEM_TOTAL);
    attn_kernel<<<NB, 256, SMEM_TOTAL>>>(queries, keys, keys_id,
                                         W1, b1, W2, b2, W3, b3, out);
}